// round 6
// baseline (speedup 1.0000x reference)
#include <cuda_runtime.h>
#include <cuda_bf16.h>

#define NN 100000
#define EE 1600000
#define DIN 24
#define DH 64
#define DOUT 12
#define NEG_SLOPE 0.01f

// ---------------- scratch (static device globals; allocation-free) -----------
__device__ __align__(16) float g_h[NN * DH];     // current node features
__device__ __align__(16) float g_hs[NN * DH];    // h @ W_self.T
__device__ __align__(16) float g_z[NN * DH];     // h @ W_func.T
__device__ float g_ssrc[NN];
__device__ float g_sdst[NN];
__device__ int   g_rowstart[NN + 1];
__device__ int   g_cursor[NN];                   // histogram counts / scatter cursor
__device__ __align__(16) int2 g_edge[EE];        // (src, bitcast(e_w)) sorted by dst
__device__ int   g_blocksums[128];
__device__ float g_c[4];                         // {c1_l1, c0_l1, c1_l2, c0_l2}

__global__ void k_nop() {}

// ---------------- tiny: per-layer edge scalar coefficients -------------------
__global__ void k_coeffs(const float* __restrict__ eW, const float* __restrict__ eb,
                         const float* __restrict__ a1, const float* __restrict__ a2) {
    __shared__ float sh[4][64];
    int j = threadIdx.x;
    sh[0][j] = eW[j] * a1[128 + j];
    sh[1][j] = eb[j] * a1[128 + j];
    sh[2][j] = eW[j] * a2[128 + j];
    sh[3][j] = eb[j] * a2[128 + j];
    __syncthreads();
    if (j < 4) {
        float s = 0.f;
        #pragma unroll
        for (int k = 0; k < 64; k++) s += sh[j][k];
        g_c[j] = s;
    }
}

// ---------------- input embedding: h = feats @ emb_h_W.T + b -----------------
__global__ void k_embed(const float* __restrict__ feats, const float* __restrict__ W,
                        const float* __restrict__ b) {
    __shared__ float w_sm[64 * 25];
    __shared__ float f_sm[4 * 25];
    __shared__ float b_sm[64];
    int t = threadIdx.x;
    int node0 = blockIdx.x * 4;
    for (int idx = t; idx < 64 * 24; idx += 256)
        w_sm[(idx / 24) * 25 + (idx % 24)] = W[idx];
    for (int idx = t; idx < 4 * 24; idx += 256)
        f_sm[(idx / 24) * 25 + (idx % 24)] = feats[(node0 + idx / 24) * 24 + (idx % 24)];
    if (t < 64) b_sm[t] = b[t];
    __syncthreads();
    int ch = t & 63, nl = t >> 6;
    float acc = b_sm[ch];
    #pragma unroll
    for (int k = 0; k < 24; k++)
        acc += f_sm[nl * 25 + k] * w_sm[ch * 25 + k];
    g_h[(node0 + nl) * 64 + ch] = acc;
}

// ---------------- CSR build --------------------------------------------------
__global__ void k_hist(const int* __restrict__ dst) {
    int e = blockIdx.x * 256 + threadIdx.x;
    atomicAdd(&g_cursor[dst[e]], 1);
}

// scan of counts -> rowstart (per-block); also zeroes cursor for the scatter pass
__global__ void k_scan1() {
    __shared__ int sh[256];
    int t = threadIdx.x;
    int base = blockIdx.x * 1024 + t * 4;
    int v[4];
    #pragma unroll
    for (int i = 0; i < 4; i++) v[i] = (base + i < NN) ? g_cursor[base + i] : 0;
    #pragma unroll
    for (int i = 0; i < 4; i++) if (base + i < NN) g_cursor[base + i] = 0;
    int s = v[0] + v[1] + v[2] + v[3];
    sh[t] = s;
    __syncthreads();
    for (int off = 1; off < 256; off <<= 1) {
        int x = 0;
        if (t >= off) x = sh[t - off];
        __syncthreads();
        if (t >= off) sh[t] += x;
        __syncthreads();
    }
    int run = sh[t] - s;  // exclusive
    #pragma unroll
    for (int i = 0; i < 4; i++) {
        if (base + i < NN) g_rowstart[base + i] = run;
        run += v[i];
    }
    if (t == 255) g_blocksums[blockIdx.x] = sh[255];
}

// adds inter-block prefix (reduction of blocksums per block)
__global__ void k_scan3() {
    __shared__ int sred[256];
    int t = threadIdx.x;
    int v = 0;
    if (t < (int)blockIdx.x && t < 128) v = g_blocksums[t];
    sred[t] = v;
    __syncthreads();
    #pragma unroll
    for (int s = 128; s > 0; s >>= 1) {
        if (t < s) sred[t] += sred[t + s];
        __syncthreads();
    }
    int add = sred[0];
    int base = blockIdx.x * 1024 + t * 4;
    #pragma unroll
    for (int i = 0; i < 4; i++)
        if (base + i < NN) g_rowstart[base + i] += add;
    if (blockIdx.x == 0 && t == 0) g_rowstart[NN] = EE;
}

__global__ void k_scatter(const int* __restrict__ src, const int* __restrict__ dst,
                          const float* __restrict__ ew) {
    int e = blockIdx.x * 256 + threadIdx.x;
    int d = dst[e];
    int p = g_rowstart[d] + atomicAdd(&g_cursor[d], 1);
    g_edge[p] = make_int2(src[e], __float_as_int(ew[e]));
}

// ---------------- node transform + fused attention scores --------------------
// hs = h@Ws.T, z = h@Wf.T; s_src = z@a_src, s_dst = z@a_dst via smem reduce.
__global__ __launch_bounds__(256) void k_xform(const float* __restrict__ Wself,
                                               const float* __restrict__ Wfunc,
                                               const float* __restrict__ attn) {
    __shared__ float4 h_sm[16][16];
    __shared__ float s_part[2][16][64];      // [score][node][ch] partials (8KB)
    int t = threadIdx.x;
    int ch = t & 63;
    int sel = t >> 6;            // 0..3
    int mat = sel >> 1;          // 0 = self, 1 = func
    int half = sel & 1;          // node half
    int node0 = blockIdx.x * 16;

    {   // load 16 x 64 h tile (256 float4, one per thread)
        int nn = t >> 4, kk = t & 15;
        h_sm[nn][kk] = ((const float4*)g_h)[(node0 + nn) * 16 + kk];
    }
    __syncthreads();

    const float4* W4 = (const float4*)((mat ? Wfunc : Wself) + ch * 64);
    float4 w4[16];
    #pragma unroll
    for (int i = 0; i < 16; i++) w4[i] = W4[i];

    float acc[8];
    #pragma unroll
    for (int n = 0; n < 8; n++) acc[n] = 0.f;

    #pragma unroll
    for (int k = 0; k < 16; k++) {
        float4 wv = w4[k];
        #pragma unroll
        for (int n = 0; n < 8; n++) {
            float4 hv = h_sm[half * 8 + n][k];
            acc[n] += wv.x * hv.x;
            acc[n] += wv.y * hv.y;
            acc[n] += wv.z * hv.z;
            acc[n] += wv.w * hv.w;
        }
    }
    float* out = mat ? g_z : g_hs;
    #pragma unroll
    for (int n = 0; n < 8; n++)
        out[(node0 + half * 8 + n) * 64 + ch] = acc[n];

    // fused scores: z-producing threads write weighted partials to smem
    if (mat) {
        float as = attn[ch];
        float ad = attn[64 + ch];
        #pragma unroll
        for (int n = 0; n < 8; n++) {
            s_part[0][half * 8 + n][ch] = acc[n] * as;
            s_part[1][half * 8 + n][ch] = acc[n] * ad;
        }
    }
    __syncthreads();
    if (t < 32) {
        int node = t & 15, sc = t >> 4;
        const float4* p = (const float4*)&s_part[sc][node][0];
        float4 s4 = p[0];
        #pragma unroll
        for (int k = 1; k < 16; k++) {
            float4 v = p[k];
            s4.x += v.x; s4.y += v.y; s4.z += v.z; s4.w += v.w;
        }
        float s = (s4.x + s4.y) + (s4.z + s4.w);
        (sc ? g_sdst : g_ssrc)[node0 + node] = s;
    }
}

// ---------------- edge aggregation + node epilogue (warp per node) -----------
// layer 0: writes updated h. layer 1: fused final projection, writes y only.
__global__ __launch_bounds__(256) void k_agg(int layer, const float* __restrict__ linW,
                                             const float* __restrict__ linb,
                                             float* __restrict__ out) {
    __shared__ float w_sm[12][64];
    __shared__ float b_sm[12];
    int t = threadIdx.x;
    if (layer) {
        for (int idx = t; idx < 12 * 64; idx += 256)
            w_sm[idx >> 6][idx & 63] = linW[idx];
        if (t < 12) b_sm[t] = linb[t];
    }
    __syncthreads();

    int n = blockIdx.x * 8 + (t >> 5);
    int lane = t & 31;
    float c1 = g_c[layer * 2 + 0];
    float c0 = g_c[layer * 2 + 1];
    int beg = g_rowstart[n];
    int end = g_rowstart[n + 1];
    float base = g_sdst[n] + c0;

    float a0 = 0.f, a1 = 0.f, den = 0.f;
    int i = beg;

    for (; i + 4 <= end; i += 4) {
        int2 e0 = g_edge[i + 0];
        int2 e1 = g_edge[i + 1];
        int2 e2 = g_edge[i + 2];
        int2 e3 = g_edge[i + 3];
        float t0 = g_ssrc[e0.x];
        float t1 = g_ssrc[e1.x];
        float t2 = g_ssrc[e2.x];
        float t3 = g_ssrc[e3.x];
        const float* z0 = g_z + (size_t)e0.x * 64;
        const float* z1 = g_z + (size_t)e1.x * 64;
        const float* z2 = g_z + (size_t)e2.x * 64;
        const float* z3 = g_z + (size_t)e3.x * 64;
        float z00 = z0[lane], z01 = z0[lane + 32];
        float z10 = z1[lane], z11 = z1[lane + 32];
        float z20 = z2[lane], z21 = z2[lane + 32];
        float z30 = z3[lane], z31 = z3[lane + 32];

        float v0 = t0 + base + c1 * __int_as_float(e0.y);
        float v1 = t1 + base + c1 * __int_as_float(e1.y);
        float v2 = t2 + base + c1 * __int_as_float(e2.y);
        float v3 = t3 + base + c1 * __int_as_float(e3.y);
        v0 = fmaxf(v0, NEG_SLOPE * v0);
        v1 = fmaxf(v1, NEG_SLOPE * v1);
        v2 = fmaxf(v2, NEG_SLOPE * v2);
        v3 = fmaxf(v3, NEG_SLOPE * v3);
        float x0 = __expf(v0), x1 = __expf(v1), x2 = __expf(v2), x3 = __expf(v3);

        den += (x0 + x1) + (x2 + x3);
        a0 += x0 * z00; a1 += x0 * z01;
        a0 += x1 * z10; a1 += x1 * z11;
        a0 += x2 * z20; a1 += x2 * z21;
        a0 += x3 * z30; a1 += x3 * z31;
    }
    for (; i < end; i++) {
        int2 e0 = g_edge[i];
        float e = g_ssrc[e0.x] + base + c1 * __int_as_float(e0.y);
        e = fmaxf(e, NEG_SLOPE * e);
        float ex = __expf(e);
        const float* zr = g_z + (size_t)e0.x * 64;
        den += ex;
        a0 += ex * zr[lane];
        a1 += ex * zr[lane + 32];
    }

    size_t o = (size_t)n * 64;
    float h0 = g_h[o + lane];
    float h1 = g_h[o + lane + 32];
    float r0, r1;
    if (end > beg) {
        float inv = 1.0f / den;
        r0 = g_hs[o + lane] + a0 * inv;
        r1 = g_hs[o + lane + 32] + a1 * inv;
    } else {
        r0 = h0; r1 = h1;
    }
    float hn0 = h0 + fmaxf(r0, 0.f);
    float hn1 = h1 + fmaxf(r1, 0.f);

    if (!layer) {
        g_h[o + lane] = hn0;
        g_h[o + lane + 32] = hn1;
    } else {
        // fused final projection: y[n] = h_new @ linW.T + b
        float yv = 0.f;
        #pragma unroll
        for (int c = 0; c < 12; c++) {
            float p = hn0 * w_sm[c][lane] + hn1 * w_sm[c][lane + 32];
            #pragma unroll
            for (int off = 16; off > 0; off >>= 1)
                p += __shfl_xor_sync(0xffffffffu, p, off);
            if (lane == c) yv = p + b_sm[c];
        }
        if (lane < 12) out[n * 12 + lane] = yv;
    }
}

// ---------------- launch -----------------------------------------------------
extern "C" void kernel_launch(void* const* d_in, const int* in_sizes, int n_in,
                              void* d_out, int out_size) {
    const float* feats   = (const float*)d_in[0];
    const float* e_w     = (const float*)d_in[1];
    const int*   src     = (const int*)d_in[4];
    const int*   dst     = (const int*)d_in[5];
    const float* emb_h_W = (const float*)d_in[6];
    const float* emb_h_b = (const float*)d_in[7];
    const float* emb_e_W = (const float*)d_in[8];
    const float* emb_e_b = (const float*)d_in[9];
    const float* W_self1 = (const float*)d_in[10];
    const float* W_func1 = (const float*)d_in[11];
    const float* attn1   = (const float*)d_in[12];
    const float* W_self2 = (const float*)d_in[13];
    const float* W_func2 = (const float*)d_in[14];
    const float* attn2   = (const float*)d_in[15];
    const float* lin1_W  = (const float*)d_in[16];
    const float* lin1_b  = (const float*)d_in[17];
    float* out = (float*)d_out;

    void* curs = nullptr;
    cudaGetSymbolAddress(&curs, g_cursor);

    const int NB_SCAN = (NN + 1023) / 1024;  // 98

    // ncu captures the 4th kernel launch (index 3; memsets don't count)
    k_coeffs<<<1, 64>>>(emb_e_W, emb_e_b, attn1, attn2);     // 0
    k_embed<<<NN / 4, 256>>>(feats, emb_h_W, emb_h_b);       // 1
    k_nop<<<1, 32>>>();                                      // 2
    k_xform<<<NN / 16, 256>>>(W_self1, W_func1, attn1);      // 3  <- ncu target

    // CSR build (dst-sorted edge lists)
    cudaMemsetAsync(curs, 0, NN * sizeof(int));
    k_hist<<<EE / 256, 256>>>(dst);
    k_scan1<<<NB_SCAN, 256>>>();
    k_scan3<<<NB_SCAN, 256>>>();
    k_scatter<<<EE / 256, 256>>>(src, dst, e_w);

    // layer 1 (xform+scores already launched above)
    k_agg<<<NN / 8, 256>>>(0, lin1_W, lin1_b, out);
    // layer 2 + fused final projection
    k_xform<<<NN / 16, 256>>>(W_self2, W_func2, attn2);
    k_agg<<<NN / 8, 256>>>(1, lin1_W, lin1_b, out);
}

// round 7
// speedup vs baseline: 1.5117x; 1.5117x over previous
#include <cuda_runtime.h>
#include <cuda_bf16.h>

#define NN 100000
#define EE 1600000
#define DIN 24
#define DH 64
#define DOUT 12
#define NEG_SLOPE 0.01f

// ---------------- scratch (static device globals; allocation-free) -----------
__device__ __align__(16) float g_h[NN * DH];     // current node features
__device__ __align__(16) float g_hs[NN * DH];    // h @ W_self.T
__device__ __align__(16) float g_z[NN * DH];     // h @ W_func.T
__device__ float g_ssrc[NN];
__device__ float g_sdst[NN];
__device__ int   g_rowstart[NN + 1];
__device__ int   g_cursor[NN];                   // histogram counts / scatter cursor
__device__ __align__(16) int2 g_edge[EE];        // (src, bitcast(e_w)) sorted by dst
__device__ int   g_blocksums[128];
__device__ float g_c[4];                         // {c1_l1, c0_l1, c1_l2, c0_l2}

__global__ void k_nop() {}

// ---------------- tiny: per-layer edge scalar coefficients -------------------
__global__ void k_coeffs(const float* __restrict__ eW, const float* __restrict__ eb,
                         const float* __restrict__ a1, const float* __restrict__ a2) {
    __shared__ float sh[4][64];
    int j = threadIdx.x;
    sh[0][j] = eW[j] * a1[128 + j];
    sh[1][j] = eb[j] * a1[128 + j];
    sh[2][j] = eW[j] * a2[128 + j];
    sh[3][j] = eb[j] * a2[128 + j];
    __syncthreads();
    if (j < 4) {
        float s = 0.f;
        #pragma unroll
        for (int k = 0; k < 64; k++) s += sh[j][k];
        g_c[j] = s;
    }
}

// ---------------- input embedding: h = feats @ emb_h_W.T + b -----------------
__global__ void k_embed(const float* __restrict__ feats, const float* __restrict__ W,
                        const float* __restrict__ b) {
    __shared__ float w_sm[64 * 25];
    __shared__ float f_sm[4 * 25];
    __shared__ float b_sm[64];
    int t = threadIdx.x;
    int node0 = blockIdx.x * 4;
    for (int idx = t; idx < 64 * 24; idx += 256)
        w_sm[(idx / 24) * 25 + (idx % 24)] = W[idx];
    for (int idx = t; idx < 4 * 24; idx += 256)
        f_sm[(idx / 24) * 25 + (idx % 24)] = feats[(node0 + idx / 24) * 24 + (idx % 24)];
    if (t < 64) b_sm[t] = b[t];
    __syncthreads();
    int ch = t & 63, nl = t >> 6;
    float acc = b_sm[ch];
    #pragma unroll
    for (int k = 0; k < 24; k++)
        acc += f_sm[nl * 25 + k] * w_sm[ch * 25 + k];
    g_h[(node0 + nl) * 64 + ch] = acc;
}

// ---------------- CSR build --------------------------------------------------
__global__ void k_hist(const int* __restrict__ dst) {
    int e = blockIdx.x * 256 + threadIdx.x;
    atomicAdd(&g_cursor[dst[e]], 1);
}

// scan of counts -> rowstart (per-block); also zeroes cursor for the scatter pass
__global__ void k_scan1() {
    __shared__ int sh[256];
    int t = threadIdx.x;
    int base = blockIdx.x * 1024 + t * 4;
    int v[4];
    #pragma unroll
    for (int i = 0; i < 4; i++) v[i] = (base + i < NN) ? g_cursor[base + i] : 0;
    #pragma unroll
    for (int i = 0; i < 4; i++) if (base + i < NN) g_cursor[base + i] = 0;
    int s = v[0] + v[1] + v[2] + v[3];
    sh[t] = s;
    __syncthreads();
    for (int off = 1; off < 256; off <<= 1) {
        int x = 0;
        if (t >= off) x = sh[t - off];
        __syncthreads();
        if (t >= off) sh[t] += x;
        __syncthreads();
    }
    int run = sh[t] - s;  // exclusive
    #pragma unroll
    for (int i = 0; i < 4; i++) {
        if (base + i < NN) g_rowstart[base + i] = run;
        run += v[i];
    }
    if (t == 255) g_blocksums[blockIdx.x] = sh[255];
}

// adds inter-block prefix (reduction of blocksums per block)
__global__ void k_scan3() {
    __shared__ int sred[256];
    int t = threadIdx.x;
    int v = 0;
    if (t < (int)blockIdx.x && t < 128) v = g_blocksums[t];
    sred[t] = v;
    __syncthreads();
    #pragma unroll
    for (int s = 128; s > 0; s >>= 1) {
        if (t < s) sred[t] += sred[t + s];
        __syncthreads();
    }
    int add = sred[0];
    int base = blockIdx.x * 1024 + t * 4;
    #pragma unroll
    for (int i = 0; i < 4; i++)
        if (base + i < NN) g_rowstart[base + i] += add;
    if (blockIdx.x == 0 && t == 0) g_rowstart[NN] = EE;
}

__global__ void k_scatter(const int* __restrict__ src, const int* __restrict__ dst,
                          const float* __restrict__ ew) {
    int e = blockIdx.x * 256 + threadIdx.x;
    int d = dst[e];
    int p = g_rowstart[d] + atomicAdd(&g_cursor[d], 1);
    g_edge[p] = make_int2(src[e], __float_as_int(ew[e]));
}

// ---------------- node transform + fused attention scores --------------------
// Register-tiled: 64 nodes/block; thread computes 4ch x 8node for one matrix.
// wT[mat][k][ch], hT[k][node] transposed in smem -> 3 LDS.128 per 32 FFMA.
__global__ __launch_bounds__(256) void k_xform(const float* __restrict__ Wself,
                                               const float* __restrict__ Wfunc,
                                               const float* __restrict__ attn) {
    __shared__ float wT[2][64][64];   // 32KB  [mat][k][ch]
    __shared__ float hT[64][64];      // 16KB  [k][node]; reused for score partials
    int t = threadIdx.x;
    int node0 = blockIdx.x * 64;

    // stage W (both matrices), transposed. Lanes span ch -> conflict-free STS.
    {
        int lch = t & 63;
        int kg0 = t >> 6;  // 0..3
        #pragma unroll
        for (int m = 0; m < 2; m++) {
            const float* Wm = m ? Wfunc : Wself;
            #pragma unroll
            for (int i = 0; i < 4; i++) {
                int kg = kg0 + i * 4;  // 0..15
                float4 wv = *(const float4*)(Wm + lch * 64 + kg * 4);
                wT[m][kg * 4 + 0][lch] = wv.x;
                wT[m][kg * 4 + 1][lch] = wv.y;
                wT[m][kg * 4 + 2][lch] = wv.z;
                wT[m][kg * 4 + 3][lch] = wv.w;
            }
        }
    }
    // stage h transposed. Lanes span node -> conflict-free STS.
    {
        int node = t & 63;
        int kg0 = t >> 6;
        int gn = node0 + node;
        #pragma unroll
        for (int i = 0; i < 4; i++) {
            int kg = kg0 + i * 4;
            float4 hv = (gn < NN) ? *(const float4*)(g_h + (size_t)gn * 64 + kg * 4)
                                  : make_float4(0.f, 0.f, 0.f, 0.f);
            hT[kg * 4 + 0][node] = hv.x;
            hT[kg * 4 + 1][node] = hv.y;
            hT[kg * 4 + 2][node] = hv.z;
            hT[kg * 4 + 3][node] = hv.w;
        }
    }
    __syncthreads();

    int ch0 = (t & 15) * 4;
    int ng  = (t >> 4) & 7;   // 8 node-groups of 8
    int mat = t >> 7;         // 0 = self, 1 = func

    float acc[8][4];
    #pragma unroll
    for (int n = 0; n < 8; n++)
        #pragma unroll
        for (int c = 0; c < 4; c++) acc[n][c] = 0.f;

    #pragma unroll 8
    for (int k = 0; k < 64; k++) {
        float4 wv = *(const float4*)&wT[mat][k][ch0];
        float4 ha = *(const float4*)&hT[k][ng * 8];
        float4 hb = *(const float4*)&hT[k][ng * 8 + 4];
        float wr[4] = {wv.x, wv.y, wv.z, wv.w};
        float hr[8] = {ha.x, ha.y, ha.z, ha.w, hb.x, hb.y, hb.z, hb.w};
        #pragma unroll
        for (int n = 0; n < 8; n++)
            #pragma unroll
            for (int c = 0; c < 4; c++)
                acc[n][c] += hr[n] * wr[c];
    }

    float* out = mat ? g_z : g_hs;
    #pragma unroll
    for (int n = 0; n < 8; n++) {
        int gn = node0 + ng * 8 + n;
        if (gn < NN)
            *(float4*)(out + (size_t)gn * 64 + ch0) =
                make_float4(acc[n][0], acc[n][1], acc[n][2], acc[n][3]);
    }

    // fused scores: reuse hT smem as partials [2][64 nodes][16 chgrps]
    __syncthreads();
    float* sp = &hT[0][0];
    if (mat) {
        float as0 = attn[ch0 + 0], as1 = attn[ch0 + 1];
        float as2 = attn[ch0 + 2], as3 = attn[ch0 + 3];
        float ad0 = attn[64 + ch0 + 0], ad1 = attn[64 + ch0 + 1];
        float ad2 = attn[64 + ch0 + 2], ad3 = attn[64 + ch0 + 3];
        int cg = t & 15;
        #pragma unroll
        for (int n = 0; n < 8; n++) {
            int node = ng * 8 + n;
            sp[node * 16 + cg] =
                acc[n][0] * as0 + acc[n][1] * as1 + acc[n][2] * as2 + acc[n][3] * as3;
            sp[1024 + node * 16 + cg] =
                acc[n][0] * ad0 + acc[n][1] * ad1 + acc[n][2] * ad2 + acc[n][3] * ad3;
        }
    }
    __syncthreads();
    if (t < 128) {
        int node = t & 63, sc = t >> 6;
        const float4* p = (const float4*)(sp + sc * 1024 + node * 16);
        float4 a = p[0], b = p[1], c = p[2], d = p[3];
        float s = ((a.x + a.y) + (a.z + a.w)) + ((b.x + b.y) + (b.z + b.w))
                + ((c.x + c.y) + (c.z + c.w)) + ((d.x + d.y) + (d.z + d.w));
        int gn = node0 + node;
        if (gn < NN) (sc ? g_sdst : g_ssrc)[gn] = s;
    }
}

// ---------------- edge aggregation + node epilogue (warp per node) -----------
// layer 0: writes updated h. layer 1: fused final projection, writes y only.
__global__ __launch_bounds__(256) void k_agg(int layer, const float* __restrict__ linW,
                                             const float* __restrict__ linb,
                                             float* __restrict__ out) {
    __shared__ float w_sm[12][64];
    __shared__ float b_sm[12];
    int t = threadIdx.x;
    if (layer) {
        for (int idx = t; idx < 12 * 64; idx += 256)
            w_sm[idx >> 6][idx & 63] = linW[idx];
        if (t < 12) b_sm[t] = linb[t];
    }
    __syncthreads();

    int n = blockIdx.x * 8 + (t >> 5);
    int lane = t & 31;
    float c1 = g_c[layer * 2 + 0];
    float c0 = g_c[layer * 2 + 1];
    int beg = g_rowstart[n];
    int end = g_rowstart[n + 1];
    float base = g_sdst[n] + c0;

    float a0 = 0.f, a1 = 0.f, den = 0.f;
    int i = beg;

    for (; i + 4 <= end; i += 4) {
        int2 e0 = g_edge[i + 0];
        int2 e1 = g_edge[i + 1];
        int2 e2 = g_edge[i + 2];
        int2 e3 = g_edge[i + 3];
        float t0 = g_ssrc[e0.x];
        float t1 = g_ssrc[e1.x];
        float t2 = g_ssrc[e2.x];
        float t3 = g_ssrc[e3.x];
        const float* z0 = g_z + (size_t)e0.x * 64;
        const float* z1 = g_z + (size_t)e1.x * 64;
        const float* z2 = g_z + (size_t)e2.x * 64;
        const float* z3 = g_z + (size_t)e3.x * 64;
        float z00 = z0[lane], z01 = z0[lane + 32];
        float z10 = z1[lane], z11 = z1[lane + 32];
        float z20 = z2[lane], z21 = z2[lane + 32];
        float z30 = z3[lane], z31 = z3[lane + 32];

        float v0 = t0 + base + c1 * __int_as_float(e0.y);
        float v1 = t1 + base + c1 * __int_as_float(e1.y);
        float v2 = t2 + base + c1 * __int_as_float(e2.y);
        float v3 = t3 + base + c1 * __int_as_float(e3.y);
        v0 = fmaxf(v0, NEG_SLOPE * v0);
        v1 = fmaxf(v1, NEG_SLOPE * v1);
        v2 = fmaxf(v2, NEG_SLOPE * v2);
        v3 = fmaxf(v3, NEG_SLOPE * v3);
        float x0 = __expf(v0), x1 = __expf(v1), x2 = __expf(v2), x3 = __expf(v3);

        den += (x0 + x1) + (x2 + x3);
        a0 += x0 * z00; a1 += x0 * z01;
        a0 += x1 * z10; a1 += x1 * z11;
        a0 += x2 * z20; a1 += x2 * z21;
        a0 += x3 * z30; a1 += x3 * z31;
    }
    for (; i < end; i++) {
        int2 e0 = g_edge[i];
        float e = g_ssrc[e0.x] + base + c1 * __int_as_float(e0.y);
        e = fmaxf(e, NEG_SLOPE * e);
        float ex = __expf(e);
        const float* zr = g_z + (size_t)e0.x * 64;
        den += ex;
        a0 += ex * zr[lane];
        a1 += ex * zr[lane + 32];
    }

    size_t o = (size_t)n * 64;
    float h0 = g_h[o + lane];
    float h1 = g_h[o + lane + 32];
    float r0, r1;
    if (end > beg) {
        float inv = 1.0f / den;
        r0 = g_hs[o + lane] + a0 * inv;
        r1 = g_hs[o + lane + 32] + a1 * inv;
    } else {
        r0 = h0; r1 = h1;
    }
    float hn0 = h0 + fmaxf(r0, 0.f);
    float hn1 = h1 + fmaxf(r1, 0.f);

    if (!layer) {
        g_h[o + lane] = hn0;
        g_h[o + lane + 32] = hn1;
    } else {
        // fused final projection: y[n] = h_new @ linW.T + b
        float yv = 0.f;
        #pragma unroll
        for (int c = 0; c < 12; c++) {
            float p = hn0 * w_sm[c][lane] + hn1 * w_sm[c][lane + 32];
            #pragma unroll
            for (int off = 16; off > 0; off >>= 1)
                p += __shfl_xor_sync(0xffffffffu, p, off);
            if (lane == c) yv = p + b_sm[c];
        }
        if (lane < 12) out[n * 12 + lane] = yv;
    }
}

// ---------------- launch -----------------------------------------------------
extern "C" void kernel_launch(void* const* d_in, const int* in_sizes, int n_in,
                              void* d_out, int out_size) {
    const float* feats   = (const float*)d_in[0];
    const float* e_w     = (const float*)d_in[1];
    const int*   src     = (const int*)d_in[4];
    const int*   dst     = (const int*)d_in[5];
    const float* emb_h_W = (const float*)d_in[6];
    const float* emb_h_b = (const float*)d_in[7];
    const float* emb_e_W = (const float*)d_in[8];
    const float* emb_e_b = (const float*)d_in[9];
    const float* W_self1 = (const float*)d_in[10];
    const float* W_func1 = (const float*)d_in[11];
    const float* attn1   = (const float*)d_in[12];
    const float* W_self2 = (const float*)d_in[13];
    const float* W_func2 = (const float*)d_in[14];
    const float* attn2   = (const float*)d_in[15];
    const float* lin1_W  = (const float*)d_in[16];
    const float* lin1_b  = (const float*)d_in[17];
    float* out = (float*)d_out;

    void* curs = nullptr;
    cudaGetSymbolAddress(&curs, g_cursor);

    const int NB_SCAN = (NN + 1023) / 1024;  // 98
    const int XB = (NN + 63) / 64;           // 1563

    // ncu captures the 4th kernel launch (index 3; memsets don't count)
    k_coeffs<<<1, 64>>>(emb_e_W, emb_e_b, attn1, attn2);     // 0
    k_embed<<<NN / 4, 256>>>(feats, emb_h_W, emb_h_b);       // 1
    k_nop<<<1, 32>>>();                                      // 2
    k_xform<<<XB, 256>>>(W_self1, W_func1, attn1);           // 3  <- ncu target

    // CSR build (dst-sorted edge lists)
    cudaMemsetAsync(curs, 0, NN * sizeof(int));
    k_hist<<<EE / 256, 256>>>(dst);
    k_scan1<<<NB_SCAN, 256>>>();
    k_scan3<<<NB_SCAN, 256>>>();
    k_scatter<<<EE / 256, 256>>>(src, dst, e_w);

    // layer 1 (xform+scores already launched above)
    k_agg<<<NN / 8, 256>>>(0, lin1_W, lin1_b, out);
    // layer 2 + fused final projection
    k_xform<<<XB, 256>>>(W_self2, W_func2, attn2);
    k_agg<<<NN / 8, 256>>>(1, lin1_W, lin1_b, out);
}

// round 8
// speedup vs baseline: 1.5825x; 1.0468x over previous
#include <cuda_runtime.h>
#include <cuda_bf16.h>
#include <cuda_fp16.h>

#define NN 100000
#define EE 1600000
#define DIN 24
#define DH 64
#define DOUT 12
#define NEG_SLOPE 0.01f

// ---------------- scratch (static device globals; allocation-free) -----------
__device__ __align__(16) float  g_h[NN * DH];    // current node features
__device__ __align__(16) float  g_hs[NN * DH];   // h @ W_self.T
__device__ __align__(16) __half g_zh[NN * DH];   // h @ W_func.T (fp16, for gathers)
__device__ float g_ssrc[NN];
__device__ float g_sdst[NN];
__device__ int   g_rowstart[NN + 1];
__device__ int   g_cursor[NN];                   // histogram counts / scatter cursor
__device__ __align__(16) int2 g_edge[EE];        // (src, bitcast(e_w)) sorted by dst
__device__ int   g_blocksums[128];
__device__ float g_c[4];                         // {c1_l1, c0_l1, c1_l2, c0_l2}

__global__ void k_nop() {}

// ---------------- tiny: per-layer edge scalar coefficients -------------------
__global__ void k_coeffs(const float* __restrict__ eW, const float* __restrict__ eb,
                         const float* __restrict__ a1, const float* __restrict__ a2) {
    __shared__ float sh[4][64];
    int j = threadIdx.x;
    sh[0][j] = eW[j] * a1[128 + j];
    sh[1][j] = eb[j] * a1[128 + j];
    sh[2][j] = eW[j] * a2[128 + j];
    sh[3][j] = eb[j] * a2[128 + j];
    __syncthreads();
    if (j < 4) {
        float s = 0.f;
        #pragma unroll
        for (int k = 0; k < 64; k++) s += sh[j][k];
        g_c[j] = s;
    }
}

// ---------------- input embedding: h = feats @ emb_h_W.T + b -----------------
__global__ void k_embed(const float* __restrict__ feats, const float* __restrict__ W,
                        const float* __restrict__ b) {
    __shared__ float w_sm[64 * 25];
    __shared__ float f_sm[4 * 25];
    __shared__ float b_sm[64];
    int t = threadIdx.x;
    int node0 = blockIdx.x * 4;
    for (int idx = t; idx < 64 * 24; idx += 256)
        w_sm[(idx / 24) * 25 + (idx % 24)] = W[idx];
    for (int idx = t; idx < 4 * 24; idx += 256)
        f_sm[(idx / 24) * 25 + (idx % 24)] = feats[(node0 + idx / 24) * 24 + (idx % 24)];
    if (t < 64) b_sm[t] = b[t];
    __syncthreads();
    int ch = t & 63, nl = t >> 6;
    float acc = b_sm[ch];
    #pragma unroll
    for (int k = 0; k < 24; k++)
        acc += f_sm[nl * 25 + k] * w_sm[ch * 25 + k];
    g_h[(node0 + nl) * 64 + ch] = acc;
}

// ---------------- CSR build --------------------------------------------------
__global__ void k_hist(const int* __restrict__ dst) {
    int e = blockIdx.x * 256 + threadIdx.x;
    atomicAdd(&g_cursor[dst[e]], 1);
}

// scan of counts -> rowstart (per-block); also zeroes cursor for the scatter pass
__global__ void k_scan1() {
    __shared__ int sh[256];
    int t = threadIdx.x;
    int base = blockIdx.x * 1024 + t * 4;
    int v[4];
    #pragma unroll
    for (int i = 0; i < 4; i++) v[i] = (base + i < NN) ? g_cursor[base + i] : 0;
    #pragma unroll
    for (int i = 0; i < 4; i++) if (base + i < NN) g_cursor[base + i] = 0;
    int s = v[0] + v[1] + v[2] + v[3];
    sh[t] = s;
    __syncthreads();
    for (int off = 1; off < 256; off <<= 1) {
        int x = 0;
        if (t >= off) x = sh[t - off];
        __syncthreads();
        if (t >= off) sh[t] += x;
        __syncthreads();
    }
    int run = sh[t] - s;  // exclusive
    #pragma unroll
    for (int i = 0; i < 4; i++) {
        if (base + i < NN) g_rowstart[base + i] = run;
        run += v[i];
    }
    if (t == 255) g_blocksums[blockIdx.x] = sh[255];
}

// adds inter-block prefix (reduction of blocksums per block)
__global__ void k_scan3() {
    __shared__ int sred[256];
    int t = threadIdx.x;
    int v = 0;
    if (t < (int)blockIdx.x && t < 128) v = g_blocksums[t];
    sred[t] = v;
    __syncthreads();
    #pragma unroll
    for (int s = 128; s > 0; s >>= 1) {
        if (t < s) sred[t] += sred[t + s];
        __syncthreads();
    }
    int add = sred[0];
    int base = blockIdx.x * 1024 + t * 4;
    #pragma unroll
    for (int i = 0; i < 4; i++)
        if (base + i < NN) g_rowstart[base + i] += add;
    if (blockIdx.x == 0 && t == 0) g_rowstart[NN] = EE;
}

__global__ void k_scatter(const int* __restrict__ src, const int* __restrict__ dst,
                          const float* __restrict__ ew) {
    int e = blockIdx.x * 256 + threadIdx.x;
    int d = dst[e];
    int p = g_rowstart[d] + atomicAdd(&g_cursor[d], 1);
    g_edge[p] = make_int2(src[e], __float_as_int(ew[e]));
}

// ---------------- node transform + fused attention scores --------------------
// Register-tiled: 64 nodes/block; thread computes 4ch x 8node for one matrix.
// hs written fp32; z written fp16 (half2 channel pairs) for the agg gathers.
__global__ __launch_bounds__(256) void k_xform(const float* __restrict__ Wself,
                                               const float* __restrict__ Wfunc,
                                               const float* __restrict__ attn) {
    __shared__ float wT[2][64][64];   // 32KB  [mat][k][ch]
    __shared__ float hT[64][64];      // 16KB  [k][node]; reused for score partials
    int t = threadIdx.x;
    int node0 = blockIdx.x * 64;

    // stage W (both matrices), transposed. Lanes span ch -> conflict-free STS.
    {
        int lch = t & 63;
        int kg0 = t >> 6;  // 0..3
        #pragma unroll
        for (int m = 0; m < 2; m++) {
            const float* Wm = m ? Wfunc : Wself;
            #pragma unroll
            for (int i = 0; i < 4; i++) {
                int kg = kg0 + i * 4;  // 0..15
                float4 wv = *(const float4*)(Wm + lch * 64 + kg * 4);
                wT[m][kg * 4 + 0][lch] = wv.x;
                wT[m][kg * 4 + 1][lch] = wv.y;
                wT[m][kg * 4 + 2][lch] = wv.z;
                wT[m][kg * 4 + 3][lch] = wv.w;
            }
        }
    }
    // stage h transposed. Lanes span node -> conflict-free STS.
    {
        int node = t & 63;
        int kg0 = t >> 6;
        int gn = node0 + node;
        #pragma unroll
        for (int i = 0; i < 4; i++) {
            int kg = kg0 + i * 4;
            float4 hv = (gn < NN) ? *(const float4*)(g_h + (size_t)gn * 64 + kg * 4)
                                  : make_float4(0.f, 0.f, 0.f, 0.f);
            hT[kg * 4 + 0][node] = hv.x;
            hT[kg * 4 + 1][node] = hv.y;
            hT[kg * 4 + 2][node] = hv.z;
            hT[kg * 4 + 3][node] = hv.w;
        }
    }
    __syncthreads();

    int ch0 = (t & 15) * 4;
    int ng  = (t >> 4) & 7;   // 8 node-groups of 8
    int mat = t >> 7;         // 0 = self, 1 = func

    float acc[8][4];
    #pragma unroll
    for (int n = 0; n < 8; n++)
        #pragma unroll
        for (int c = 0; c < 4; c++) acc[n][c] = 0.f;

    #pragma unroll 8
    for (int k = 0; k < 64; k++) {
        float4 wv = *(const float4*)&wT[mat][k][ch0];
        float4 ha = *(const float4*)&hT[k][ng * 8];
        float4 hb = *(const float4*)&hT[k][ng * 8 + 4];
        float wr[4] = {wv.x, wv.y, wv.z, wv.w};
        float hr[8] = {ha.x, ha.y, ha.z, ha.w, hb.x, hb.y, hb.z, hb.w};
        #pragma unroll
        for (int n = 0; n < 8; n++)
            #pragma unroll
            for (int c = 0; c < 4; c++)
                acc[n][c] += hr[n] * wr[c];
    }

    if (!mat) {
        #pragma unroll
        for (int n = 0; n < 8; n++) {
            int gn = node0 + ng * 8 + n;
            if (gn < NN)
                *(float4*)(g_hs + (size_t)gn * 64 + ch0) =
                    make_float4(acc[n][0], acc[n][1], acc[n][2], acc[n][3]);
        }
    } else {
        #pragma unroll
        for (int n = 0; n < 8; n++) {
            int gn = node0 + ng * 8 + n;
            if (gn < NN) {
                union { __half2 h2[2]; uint2 u; } cv;
                cv.h2[0] = __floats2half2_rn(acc[n][0], acc[n][1]);
                cv.h2[1] = __floats2half2_rn(acc[n][2], acc[n][3]);
                *(uint2*)(g_zh + (size_t)gn * 64 + ch0) = cv.u;
            }
        }
    }

    // fused scores: reuse hT smem as partials [2][64 nodes][16 chgrps]
    __syncthreads();
    float* sp = &hT[0][0];
    if (mat) {
        float as0 = attn[ch0 + 0], as1 = attn[ch0 + 1];
        float as2 = attn[ch0 + 2], as3 = attn[ch0 + 3];
        float ad0 = attn[64 + ch0 + 0], ad1 = attn[64 + ch0 + 1];
        float ad2 = attn[64 + ch0 + 2], ad3 = attn[64 + ch0 + 3];
        int cg = t & 15;
        #pragma unroll
        for (int n = 0; n < 8; n++) {
            int node = ng * 8 + n;
            sp[node * 16 + cg] =
                acc[n][0] * as0 + acc[n][1] * as1 + acc[n][2] * as2 + acc[n][3] * as3;
            sp[1024 + node * 16 + cg] =
                acc[n][0] * ad0 + acc[n][1] * ad1 + acc[n][2] * ad2 + acc[n][3] * ad3;
        }
    }
    __syncthreads();
    if (t < 128) {
        int node = t & 63, sc = t >> 6;
        const float4* p = (const float4*)(sp + sc * 1024 + node * 16);
        float4 a = p[0], b = p[1], c = p[2], d = p[3];
        float s = ((a.x + a.y) + (a.z + a.w)) + ((b.x + b.y) + (b.z + b.w))
                + ((c.x + c.y) + (c.z + c.w)) + ((d.x + d.y) + (d.z + d.w));
        int gn = node0 + node;
        if (gn < NN) (sc ? g_sdst : g_ssrc)[gn] = s;
    }
}

// ---------------- edge aggregation + node epilogue (warp per node) -----------
// Lane owns channels (2*lane, 2*lane+1): z gather = one half2 per lane (one
// 128B line per edge); h/hs epilogue as float2.
// layer 0: writes updated h. layer 1: fused final projection, writes y only.
__global__ __launch_bounds__(256) void k_agg(int layer, const float* __restrict__ linW,
                                             const float* __restrict__ linb,
                                             float* __restrict__ out) {
    __shared__ float w_sm[12][64];
    __shared__ float b_sm[12];
    int t = threadIdx.x;
    if (layer) {
        for (int idx = t; idx < 12 * 64; idx += 256)
            w_sm[idx >> 6][idx & 63] = linW[idx];
        if (t < 12) b_sm[t] = linb[t];
    }
    __syncthreads();

    int n = blockIdx.x * 8 + (t >> 5);
    int lane = t & 31;
    float c1 = g_c[layer * 2 + 0];
    float c0 = g_c[layer * 2 + 1];
    int beg = g_rowstart[n];
    int end = g_rowstart[n + 1];
    float base = g_sdst[n] + c0;

    float a0 = 0.f, a1 = 0.f, den = 0.f;
    int i = beg;

    for (; i + 4 <= end; i += 4) {
        int2 e0 = g_edge[i + 0];
        int2 e1 = g_edge[i + 1];
        int2 e2 = g_edge[i + 2];
        int2 e3 = g_edge[i + 3];
        float t0 = g_ssrc[e0.x];
        float t1 = g_ssrc[e1.x];
        float t2 = g_ssrc[e2.x];
        float t3 = g_ssrc[e3.x];
        __half2 zh0 = *(const __half2*)(g_zh + (size_t)e0.x * 64 + 2 * lane);
        __half2 zh1 = *(const __half2*)(g_zh + (size_t)e1.x * 64 + 2 * lane);
        __half2 zh2 = *(const __half2*)(g_zh + (size_t)e2.x * 64 + 2 * lane);
        __half2 zh3 = *(const __half2*)(g_zh + (size_t)e3.x * 64 + 2 * lane);

        float v0 = t0 + base + c1 * __int_as_float(e0.y);
        float v1 = t1 + base + c1 * __int_as_float(e1.y);
        float v2 = t2 + base + c1 * __int_as_float(e2.y);
        float v3 = t3 + base + c1 * __int_as_float(e3.y);
        v0 = fmaxf(v0, NEG_SLOPE * v0);
        v1 = fmaxf(v1, NEG_SLOPE * v1);
        v2 = fmaxf(v2, NEG_SLOPE * v2);
        v3 = fmaxf(v3, NEG_SLOPE * v3);
        float x0 = __expf(v0), x1 = __expf(v1), x2 = __expf(v2), x3 = __expf(v3);

        float2 z0 = __half22float2(zh0);
        float2 z1 = __half22float2(zh1);
        float2 z2 = __half22float2(zh2);
        float2 z3 = __half22float2(zh3);

        den += (x0 + x1) + (x2 + x3);
        a0 += x0 * z0.x; a1 += x0 * z0.y;
        a0 += x1 * z1.x; a1 += x1 * z1.y;
        a0 += x2 * z2.x; a1 += x2 * z2.y;
        a0 += x3 * z3.x; a1 += x3 * z3.y;
    }
    for (; i < end; i++) {
        int2 e0 = g_edge[i];
        float e = g_ssrc[e0.x] + base + c1 * __int_as_float(e0.y);
        e = fmaxf(e, NEG_SLOPE * e);
        float ex = __expf(e);
        float2 zf = __half22float2(*(const __half2*)(g_zh + (size_t)e0.x * 64 + 2 * lane));
        den += ex;
        a0 += ex * zf.x;
        a1 += ex * zf.y;
    }

    size_t o = (size_t)n * 64 + 2 * lane;
    float2 hv = *(const float2*)(g_h + o);
    float r0, r1;
    if (end > beg) {
        float inv = 1.0f / den;
        float2 hsv = *(const float2*)(g_hs + o);
        r0 = hsv.x + a0 * inv;
        r1 = hsv.y + a1 * inv;
    } else {
        r0 = hv.x; r1 = hv.y;
    }
    float hn0 = hv.x + fmaxf(r0, 0.f);
    float hn1 = hv.y + fmaxf(r1, 0.f);

    if (!layer) {
        *(float2*)(g_h + o) = make_float2(hn0, hn1);
    } else {
        // fused final projection: y[n] = h_new @ linW.T + b
        float yv = 0.f;
        #pragma unroll
        for (int c = 0; c < 12; c++) {
            float2 wv = *(const float2*)&w_sm[c][2 * lane];
            float p = hn0 * wv.x + hn1 * wv.y;
            #pragma unroll
            for (int off = 16; off > 0; off >>= 1)
                p += __shfl_xor_sync(0xffffffffu, p, off);
            if (lane == c) yv = p + b_sm[c];
        }
        if (lane < 12) out[n * 12 + lane] = yv;
    }
}

// ---------------- launch -----------------------------------------------------
extern "C" void kernel_launch(void* const* d_in, const int* in_sizes, int n_in,
                              void* d_out, int out_size) {
    const float* feats   = (const float*)d_in[0];
    const float* e_w     = (const float*)d_in[1];
    const int*   src     = (const int*)d_in[4];
    const int*   dst     = (const int*)d_in[5];
    const float* emb_h_W = (const float*)d_in[6];
    const float* emb_h_b = (const float*)d_in[7];
    const float* emb_e_W = (const float*)d_in[8];
    const float* emb_e_b = (const float*)d_in[9];
    const float* W_self1 = (const float*)d_in[10];
    const float* W_func1 = (const float*)d_in[11];
    const float* attn1   = (const float*)d_in[12];
    const float* W_self2 = (const float*)d_in[13];
    const float* W_func2 = (const float*)d_in[14];
    const float* attn2   = (const float*)d_in[15];
    const float* lin1_W  = (const float*)d_in[16];
    const float* lin1_b  = (const float*)d_in[17];
    float* out = (float*)d_out;

    void* curs = nullptr;
    cudaGetSymbolAddress(&curs, g_cursor);

    const int NB_SCAN = (NN + 1023) / 1024;  // 98
    const int XB = (NN + 63) / 64;           // 1563

    // ncu captures the 4th kernel launch (index 3; memsets don't count)
    k_coeffs<<<1, 64>>>(emb_e_W, emb_e_b, attn1, attn2);     // 0
    k_embed<<<NN / 4, 256>>>(feats, emb_h_W, emb_h_b);       // 1
    k_nop<<<1, 32>>>();                                      // 2
    k_xform<<<XB, 256>>>(W_self1, W_func1, attn1);           // 3  <- ncu target

    // CSR build (dst-sorted edge lists)
    cudaMemsetAsync(curs, 0, NN * sizeof(int));
    k_hist<<<EE / 256, 256>>>(dst);
    k_scan1<<<NB_SCAN, 256>>>();
    k_scan3<<<NB_SCAN, 256>>>();
    k_scatter<<<EE / 256, 256>>>(src, dst, e_w);

    // layer 1 (xform+scores already launched above)
    k_agg<<<NN / 8, 256>>>(0, lin1_W, lin1_b, out);
    // layer 2 + fused final projection
    k_xform<<<XB, 256>>>(W_self2, W_func2, attn2);
    k_agg<<<NN / 8, 256>>>(1, lin1_W, lin1_b, out);
}

// round 9
// speedup vs baseline: 1.6104x; 1.0177x over previous
#include <cuda_runtime.h>
#include <cuda_bf16.h>
#include <cuda_fp16.h>

#define NN 100000
#define EE 1600000
#define DIN 24
#define DH 64
#define DOUT 12
#define NEG_SLOPE 0.01f

// ---------------- scratch (static device globals; allocation-free) -----------
__device__ __align__(16) float  g_h[NN * DH];    // current node features
__device__ __align__(16) float  g_hs[NN * DH];   // h @ W_self.T
__device__ __align__(16) __half g_zh[NN * DH];   // h @ W_func.T (fp16, for gathers)
__device__ float g_ssrc[NN];
__device__ float g_sdst[NN];
__device__ int   g_rowstart[NN + 1];
__device__ int   g_cursor[NN];                   // counts; returns to 0 after scatter
__device__ __align__(16) int2 g_edge[EE];        // (src, bitcast(e_w)) sorted by dst
__device__ int   g_blocksums[128];
__device__ float g_c[4];                         // {c1_l1, c0_l1, c1_l2, c0_l2}

// ---------------- CSR build --------------------------------------------------
__global__ void k_hist(const int* __restrict__ dst) {
    int e = blockIdx.x * 256 + threadIdx.x;
    atomicAdd(&g_cursor[dst[e]], 1);
}

// per-block exclusive scan of counts -> rowstart (counts preserved for scatter)
__global__ void k_scan1() {
    __shared__ int sh[256];
    int t = threadIdx.x;
    int base = blockIdx.x * 1024 + t * 4;
    int v[4];
    #pragma unroll
    for (int i = 0; i < 4; i++) v[i] = (base + i < NN) ? g_cursor[base + i] : 0;
    int s = v[0] + v[1] + v[2] + v[3];
    sh[t] = s;
    __syncthreads();
    for (int off = 1; off < 256; off <<= 1) {
        int x = 0;
        if (t >= off) x = sh[t - off];
        __syncthreads();
        if (t >= off) sh[t] += x;
        __syncthreads();
    }
    int run = sh[t] - s;  // exclusive
    #pragma unroll
    for (int i = 0; i < 4; i++) {
        if (base + i < NN) g_rowstart[base + i] = run;
        run += v[i];
    }
    if (t == 255) g_blocksums[blockIdx.x] = sh[255];
}

// inter-block prefix add; block 0 also computes the per-layer edge coefficients
__global__ void k_scan3(const float* __restrict__ eW, const float* __restrict__ eb,
                        const float* __restrict__ a1, const float* __restrict__ a2) {
    __shared__ int sred[256];
    __shared__ float csh[4][64];
    int t = threadIdx.x;
    if (blockIdx.x == 0 && t < 64) {
        csh[0][t] = eW[t] * a1[128 + t];
        csh[1][t] = eb[t] * a1[128 + t];
        csh[2][t] = eW[t] * a2[128 + t];
        csh[3][t] = eb[t] * a2[128 + t];
    }
    int v = 0;
    if (t < (int)blockIdx.x && t < 128) v = g_blocksums[t];
    sred[t] = v;
    __syncthreads();
    #pragma unroll
    for (int s = 128; s > 0; s >>= 1) {
        if (t < s) sred[t] += sred[t + s];
        __syncthreads();
    }
    int add = sred[0];
    int base = blockIdx.x * 1024 + t * 4;
    #pragma unroll
    for (int i = 0; i < 4; i++)
        if (base + i < NN) g_rowstart[base + i] += add;
    if (blockIdx.x == 0 && t == 0) g_rowstart[NN] = EE;
    if (blockIdx.x == 0 && t < 4) {
        float s = 0.f;
        #pragma unroll
        for (int k = 0; k < 64; k++) s += csh[t][k];
        g_c[t] = s;
    }
}

// atomicSub leaves cursor at 0 -> replay-safe without a memset
__global__ void k_scatter(const int* __restrict__ src, const int* __restrict__ dst,
                          const float* __restrict__ ew) {
    int e = blockIdx.x * 256 + threadIdx.x;
    int d = dst[e];
    int p = g_rowstart[d] + atomicSub(&g_cursor[d], 1) - 1;
    g_edge[p] = make_int2(src[e], __float_as_int(ew[e]));
}

// ---------------- input embedding: h = feats @ emb_h_W.T + b -----------------
__global__ void k_embed(const float* __restrict__ feats, const float* __restrict__ W,
                        const float* __restrict__ b) {
    __shared__ float w_sm[64 * 25];
    __shared__ float f_sm[4 * 25];
    __shared__ float b_sm[64];
    int t = threadIdx.x;
    int node0 = blockIdx.x * 4;
    for (int idx = t; idx < 64 * 24; idx += 256)
        w_sm[(idx / 24) * 25 + (idx % 24)] = W[idx];
    for (int idx = t; idx < 4 * 24; idx += 256)
        f_sm[(idx / 24) * 25 + (idx % 24)] = feats[(node0 + idx / 24) * 24 + (idx % 24)];
    if (t < 64) b_sm[t] = b[t];
    __syncthreads();
    int ch = t & 63, nl = t >> 6;
    float acc = b_sm[ch];
    #pragma unroll
    for (int k = 0; k < 24; k++)
        acc += f_sm[nl * 25 + k] * w_sm[ch * 25 + k];
    g_h[(node0 + nl) * 64 + ch] = acc;
}

// ---------------- node transform + fused attention scores --------------------
__global__ __launch_bounds__(256) void k_xform(const float* __restrict__ Wself,
                                               const float* __restrict__ Wfunc,
                                               const float* __restrict__ attn) {
    __shared__ float wT[2][64][64];   // 32KB  [mat][k][ch]
    __shared__ float hT[64][64];      // 16KB  [k][node]; reused for score partials
    int t = threadIdx.x;
    int node0 = blockIdx.x * 64;

    {
        int lch = t & 63;
        int kg0 = t >> 6;  // 0..3
        #pragma unroll
        for (int m = 0; m < 2; m++) {
            const float* Wm = m ? Wfunc : Wself;
            #pragma unroll
            for (int i = 0; i < 4; i++) {
                int kg = kg0 + i * 4;  // 0..15
                float4 wv = *(const float4*)(Wm + lch * 64 + kg * 4);
                wT[m][kg * 4 + 0][lch] = wv.x;
                wT[m][kg * 4 + 1][lch] = wv.y;
                wT[m][kg * 4 + 2][lch] = wv.z;
                wT[m][kg * 4 + 3][lch] = wv.w;
            }
        }
    }
    {
        int node = t & 63;
        int kg0 = t >> 6;
        int gn = node0 + node;
        #pragma unroll
        for (int i = 0; i < 4; i++) {
            int kg = kg0 + i * 4;
            float4 hv = (gn < NN) ? *(const float4*)(g_h + (size_t)gn * 64 + kg * 4)
                                  : make_float4(0.f, 0.f, 0.f, 0.f);
            hT[kg * 4 + 0][node] = hv.x;
            hT[kg * 4 + 1][node] = hv.y;
            hT[kg * 4 + 2][node] = hv.z;
            hT[kg * 4 + 3][node] = hv.w;
        }
    }
    __syncthreads();

    int ch0 = (t & 15) * 4;
    int ng  = (t >> 4) & 7;   // 8 node-groups of 8
    int mat = t >> 7;         // 0 = self, 1 = func

    float acc[8][4];
    #pragma unroll
    for (int n = 0; n < 8; n++)
        #pragma unroll
        for (int c = 0; c < 4; c++) acc[n][c] = 0.f;

    #pragma unroll 8
    for (int k = 0; k < 64; k++) {
        float4 wv = *(const float4*)&wT[mat][k][ch0];
        float4 ha = *(const float4*)&hT[k][ng * 8];
        float4 hb = *(const float4*)&hT[k][ng * 8 + 4];
        float wr[4] = {wv.x, wv.y, wv.z, wv.w};
        float hr[8] = {ha.x, ha.y, ha.z, ha.w, hb.x, hb.y, hb.z, hb.w};
        #pragma unroll
        for (int n = 0; n < 8; n++)
            #pragma unroll
            for (int c = 0; c < 4; c++)
                acc[n][c] += hr[n] * wr[c];
    }

    if (!mat) {
        #pragma unroll
        for (int n = 0; n < 8; n++) {
            int gn = node0 + ng * 8 + n;
            if (gn < NN)
                *(float4*)(g_hs + (size_t)gn * 64 + ch0) =
                    make_float4(acc[n][0], acc[n][1], acc[n][2], acc[n][3]);
        }
    } else {
        #pragma unroll
        for (int n = 0; n < 8; n++) {
            int gn = node0 + ng * 8 + n;
            if (gn < NN) {
                union { __half2 h2[2]; uint2 u; } cv;
                cv.h2[0] = __floats2half2_rn(acc[n][0], acc[n][1]);
                cv.h2[1] = __floats2half2_rn(acc[n][2], acc[n][3]);
                *(uint2*)(g_zh + (size_t)gn * 64 + ch0) = cv.u;
            }
        }
    }

    __syncthreads();
    float* sp = &hT[0][0];
    if (mat) {
        float as0 = attn[ch0 + 0], as1 = attn[ch0 + 1];
        float as2 = attn[ch0 + 2], as3 = attn[ch0 + 3];
        float ad0 = attn[64 + ch0 + 0], ad1 = attn[64 + ch0 + 1];
        float ad2 = attn[64 + ch0 + 2], ad3 = attn[64 + ch0 + 3];
        int cg = t & 15;
        #pragma unroll
        for (int n = 0; n < 8; n++) {
            int node = ng * 8 + n;
            sp[node * 16 + cg] =
                acc[n][0] * as0 + acc[n][1] * as1 + acc[n][2] * as2 + acc[n][3] * as3;
            sp[1024 + node * 16 + cg] =
                acc[n][0] * ad0 + acc[n][1] * ad1 + acc[n][2] * ad2 + acc[n][3] * ad3;
        }
    }
    __syncthreads();
    if (t < 128) {
        int node = t & 63, sc = t >> 6;
        const float4* p = (const float4*)(sp + sc * 1024 + node * 16);
        float4 a = p[0], b = p[1], c = p[2], d = p[3];
        float s = ((a.x + a.y) + (a.z + a.w)) + ((b.x + b.y) + (b.z + b.w))
                + ((c.x + c.y) + (c.z + c.w)) + ((d.x + d.y) + (d.z + d.w));
        int gn = node0 + node;
        if (gn < NN) (sc ? g_sdst : g_ssrc)[gn] = s;
    }
}

// ---------------- edge aggregation + node epilogue (warp per node) -----------
// 8-wide main loop (16 independent loads in flight), 4-wide mid, scalar tail.
__global__ __launch_bounds__(256) void k_agg(int layer, const float* __restrict__ linW,
                                             const float* __restrict__ linb,
                                             float* __restrict__ out) {
    __shared__ float w_sm[12][64];
    __shared__ float b_sm[12];
    int t = threadIdx.x;
    if (layer) {
        for (int idx = t; idx < 12 * 64; idx += 256)
            w_sm[idx >> 6][idx & 63] = linW[idx];
        if (t < 12) b_sm[t] = linb[t];
    }
    __syncthreads();

    int n = blockIdx.x * 8 + (t >> 5);
    int lane = t & 31;
    float c1 = g_c[layer * 2 + 0];
    float c0 = g_c[layer * 2 + 1];
    int beg = g_rowstart[n];
    int end = g_rowstart[n + 1];
    float base = g_sdst[n] + c0;

    float a0 = 0.f, a1 = 0.f, den = 0.f;
    int i = beg;

    for (; i + 8 <= end; i += 8) {
        int2 e[8];
        float ts[8];
        __half2 zh[8];
        #pragma unroll
        for (int j = 0; j < 8; j++) e[j] = g_edge[i + j];
        #pragma unroll
        for (int j = 0; j < 8; j++) ts[j] = g_ssrc[e[j].x];
        #pragma unroll
        for (int j = 0; j < 8; j++)
            zh[j] = *(const __half2*)(g_zh + (size_t)e[j].x * 64 + 2 * lane);
        #pragma unroll
        for (int j = 0; j < 8; j++) {
            float v = ts[j] + base + c1 * __int_as_float(e[j].y);
            v = fmaxf(v, NEG_SLOPE * v);
            float x = __expf(v);
            float2 zf = __half22float2(zh[j]);
            den += x;
            a0 += x * zf.x;
            a1 += x * zf.y;
        }
    }
    for (; i + 4 <= end; i += 4) {
        int2 e[4];
        float ts[4];
        __half2 zh[4];
        #pragma unroll
        for (int j = 0; j < 4; j++) e[j] = g_edge[i + j];
        #pragma unroll
        for (int j = 0; j < 4; j++) ts[j] = g_ssrc[e[j].x];
        #pragma unroll
        for (int j = 0; j < 4; j++)
            zh[j] = *(const __half2*)(g_zh + (size_t)e[j].x * 64 + 2 * lane);
        #pragma unroll
        for (int j = 0; j < 4; j++) {
            float v = ts[j] + base + c1 * __int_as_float(e[j].y);
            v = fmaxf(v, NEG_SLOPE * v);
            float x = __expf(v);
            float2 zf = __half22float2(zh[j]);
            den += x;
            a0 += x * zf.x;
            a1 += x * zf.y;
        }
    }
    for (; i < end; i++) {
        int2 e0 = g_edge[i];
        float e = g_ssrc[e0.x] + base + c1 * __int_as_float(e0.y);
        e = fmaxf(e, NEG_SLOPE * e);
        float ex = __expf(e);
        float2 zf = __half22float2(*(const __half2*)(g_zh + (size_t)e0.x * 64 + 2 * lane));
        den += ex;
        a0 += ex * zf.x;
        a1 += ex * zf.y;
    }

    size_t o = (size_t)n * 64 + 2 * lane;
    float2 hv = *(const float2*)(g_h + o);
    float r0, r1;
    if (end > beg) {
        float inv = 1.0f / den;
        float2 hsv = *(const float2*)(g_hs + o);
        r0 = hsv.x + a0 * inv;
        r1 = hsv.y + a1 * inv;
    } else {
        r0 = hv.x; r1 = hv.y;
    }
    float hn0 = hv.x + fmaxf(r0, 0.f);
    float hn1 = hv.y + fmaxf(r1, 0.f);

    if (!layer) {
        *(float2*)(g_h + o) = make_float2(hn0, hn1);
    } else {
        float yv = 0.f;
        #pragma unroll
        for (int c = 0; c < 12; c++) {
            float2 wv = *(const float2*)&w_sm[c][2 * lane];
            float p = hn0 * wv.x + hn1 * wv.y;
            #pragma unroll
            for (int off = 16; off > 0; off >>= 1)
                p += __shfl_xor_sync(0xffffffffu, p, off);
            if (lane == c) yv = p + b_sm[c];
        }
        if (lane < 12) out[n * 12 + lane] = yv;
    }
}

// ---------------- launch -----------------------------------------------------
extern "C" void kernel_launch(void* const* d_in, const int* in_sizes, int n_in,
                              void* d_out, int out_size) {
    const float* feats   = (const float*)d_in[0];
    const float* e_w     = (const float*)d_in[1];
    const int*   src     = (const int*)d_in[4];
    const int*   dst     = (const int*)d_in[5];
    const float* emb_h_W = (const float*)d_in[6];
    const float* emb_h_b = (const float*)d_in[7];
    const float* emb_e_W = (const float*)d_in[8];
    const float* emb_e_b = (const float*)d_in[9];
    const float* W_self1 = (const float*)d_in[10];
    const float* W_func1 = (const float*)d_in[11];
    const float* attn1   = (const float*)d_in[12];
    const float* W_self2 = (const float*)d_in[13];
    const float* W_func2 = (const float*)d_in[14];
    const float* attn2   = (const float*)d_in[15];
    const float* lin1_W  = (const float*)d_in[16];
    const float* lin1_b  = (const float*)d_in[17];
    float* out = (float*)d_out;

    const int NB_SCAN = (NN + 1023) / 1024;  // 98
    const int XB = (NN + 63) / 64;           // 1563

    // CSR first (replay-safe: scatter's atomicSub returns cursor to 0).
    // ncu captures the 4th kernel launch -> k_scatter this round.
    k_hist<<<EE / 256, 256>>>(dst);                              // 0
    k_scan1<<<NB_SCAN, 256>>>();                                 // 1
    k_scan3<<<NB_SCAN, 256>>>(emb_e_W, emb_e_b, attn1, attn2);   // 2 (+coeffs)
    k_scatter<<<EE / 256, 256>>>(src, dst, e_w);                 // 3  <- ncu target

    k_embed<<<NN / 4, 256>>>(feats, emb_h_W, emb_h_b);           // 4
    k_xform<<<XB, 256>>>(W_self1, W_func1, attn1);               // 5
    k_agg<<<NN / 8, 256>>>(0, lin1_W, lin1_b, out);              // 6
    k_xform<<<XB, 256>>>(W_self2, W_func2, attn2);               // 7
    k_agg<<<NN / 8, 256>>>(1, lin1_W, lin1_b, out);              // 8
}

// round 10
// speedup vs baseline: 1.6222x; 1.0073x over previous
#include <cuda_runtime.h>
#include <cuda_bf16.h>
#include <cuda_fp16.h>

#define NN 100000
#define EE 1600000
#define DIN 24
#define DH 64
#define DOUT 12
#define NEG_SLOPE 0.01f

#define HB    (EE / 256)          // 6250 hist blocks
#define EMB   (NN / 4)            // 25000 embed blocks
#define NB_SCAN ((NN + 1023) / 1024)  // 98
#define XB    ((NN + 63) / 64)    // 1563 xform blocks

// ---------------- scratch (static device globals; allocation-free) -----------
__device__ __align__(16) float  g_h[NN * DH];    // current node features
__device__ __align__(16) float  g_hs[NN * DH];   // h @ W_self.T
__device__ __align__(16) __half g_zh[NN * DH];   // h @ W_func.T (fp16, for gathers)
__device__ float g_ssrc[NN];
__device__ float g_sdst[NN];
__device__ int   g_rowstart[NN + 1];
__device__ int   g_cursor[NN];                   // counts; returns to 0 after scatter
__device__ __align__(16) int2 g_edge[EE];        // (src, bitcast(e_w)) sorted by dst
__device__ int   g_flags[128];                   // lookback flags (reset by k_sx)
__device__ int   g_aggval[128];
__device__ int   g_prefval[128];
__device__ float g_c[4];                         // {c1_l1, c0_l1, c1_l2, c0_l2}

// ---------------- fused: hist + input embedding + edge coeffs ----------------
__global__ __launch_bounds__(256) void k_pre(
    const int* __restrict__ dst, const float* __restrict__ feats,
    const float* __restrict__ W, const float* __restrict__ b,
    const float* __restrict__ eW, const float* __restrict__ eb,
    const float* __restrict__ a1, const float* __restrict__ a2) {
    __shared__ float w_sm[64 * 25];
    __shared__ float f_sm[4 * 25];
    __shared__ float b_sm[64];
    __shared__ float csh[4][64];
    int t = threadIdx.x;
    int blk = blockIdx.x;

    if (blk < HB) {
        // histogram of dst
        int e = blk * 256 + t;
        atomicAdd(&g_cursor[dst[e]], 1);
    } else if (blk < HB + EMB) {
        // embedding: h = feats @ emb_h_W.T + b
        int node0 = (blk - HB) * 4;
        for (int idx = t; idx < 64 * 24; idx += 256)
            w_sm[(idx / 24) * 25 + (idx % 24)] = W[idx];
        for (int idx = t; idx < 4 * 24; idx += 256)
            f_sm[(idx / 24) * 25 + (idx % 24)] = feats[(node0 + idx / 24) * 24 + (idx % 24)];
        if (t < 64) b_sm[t] = b[t];
        __syncthreads();
        int ch = t & 63, nl = t >> 6;
        float acc = b_sm[ch];
        #pragma unroll
        for (int k = 0; k < 24; k++)
            acc += f_sm[nl * 25 + k] * w_sm[ch * 25 + k];
        g_h[(node0 + nl) * 64 + ch] = acc;
    } else {
        // per-layer edge scalar coefficients
        if (t < 64) {
            csh[0][t] = eW[t] * a1[128 + t];
            csh[1][t] = eb[t] * a1[128 + t];
            csh[2][t] = eW[t] * a2[128 + t];
            csh[3][t] = eb[t] * a2[128 + t];
        }
        __syncthreads();
        if (t < 4) {
            float s = 0.f;
            #pragma unroll
            for (int k = 0; k < 64; k++) s += csh[t][k];
            g_c[t] = s;
        }
    }
}

// ---------------- single-pass scan (decoupled lookback) ----------------------
// counts (g_cursor) -> exclusive prefix (g_rowstart); counts preserved.
__global__ __launch_bounds__(256) void k_scan() {
    __shared__ int sh[256];
    __shared__ int s_pref;
    int t = threadIdx.x;
    int bid = blockIdx.x;
    int base = bid * 1024 + t * 4;
    int v[4];
    #pragma unroll
    for (int i = 0; i < 4; i++) v[i] = (base + i < NN) ? g_cursor[base + i] : 0;
    int s = v[0] + v[1] + v[2] + v[3];
    sh[t] = s;
    __syncthreads();
    for (int off = 1; off < 256; off <<= 1) {
        int x = 0;
        if (t >= off) x = sh[t - off];
        __syncthreads();
        if (t >= off) sh[t] += x;
        __syncthreads();
    }
    int total = sh[255];
    int run = sh[t] - s;  // exclusive within block

    if (t == 0) {
        g_aggval[bid] = total;
        __threadfence();
        atomicExch(&g_flags[bid], 1);
        // lookback
        int pref = 0;
        int j = bid - 1;
        while (j >= 0) {
            int f;
            do { f = atomicAdd(&g_flags[j], 0); } while (f == 0);
            if (f == 2) { pref += atomicAdd(&g_prefval[j], 0); break; }
            pref += atomicAdd(&g_aggval[j], 0);
            j--;
        }
        g_prefval[bid] = pref + total;
        __threadfence();
        atomicExch(&g_flags[bid], 2);
        s_pref = pref;
    }
    __syncthreads();
    int add = s_pref;
    #pragma unroll
    for (int i = 0; i < 4; i++) {
        if (base + i < NN) g_rowstart[base + i] = add + run;
        run += v[i];
    }
    if (bid == 0 && t == 0) g_rowstart[NN] = EE;
}

// ---------------- xform body (used by k_sx and k_xform2) ---------------------
__device__ __forceinline__ void xform_body(int node0, const float* __restrict__ Wself,
                                           const float* __restrict__ Wfunc,
                                           const float* __restrict__ attn,
                                           float (*wT)[64][64], float (*hT)[64]) {
    int t = threadIdx.x;
    {
        int lch = t & 63;
        int kg0 = t >> 6;  // 0..3
        #pragma unroll
        for (int m = 0; m < 2; m++) {
            const float* Wm = m ? Wfunc : Wself;
            #pragma unroll
            for (int i = 0; i < 4; i++) {
                int kg = kg0 + i * 4;  // 0..15
                float4 wv = *(const float4*)(Wm + lch * 64 + kg * 4);
                wT[m][kg * 4 + 0][lch] = wv.x;
                wT[m][kg * 4 + 1][lch] = wv.y;
                wT[m][kg * 4 + 2][lch] = wv.z;
                wT[m][kg * 4 + 3][lch] = wv.w;
            }
        }
    }
    {
        int node = t & 63;
        int kg0 = t >> 6;
        int gn = node0 + node;
        #pragma unroll
        for (int i = 0; i < 4; i++) {
            int kg = kg0 + i * 4;
            float4 hv = (gn < NN) ? *(const float4*)(g_h + (size_t)gn * 64 + kg * 4)
                                  : make_float4(0.f, 0.f, 0.f, 0.f);
            hT[kg * 4 + 0][node] = hv.x;
            hT[kg * 4 + 1][node] = hv.y;
            hT[kg * 4 + 2][node] = hv.z;
            hT[kg * 4 + 3][node] = hv.w;
        }
    }
    __syncthreads();

    int ch0 = (t & 15) * 4;
    int ng  = (t >> 4) & 7;   // 8 node-groups of 8
    int mat = t >> 7;         // 0 = self, 1 = func

    float acc[8][4];
    #pragma unroll
    for (int n = 0; n < 8; n++)
        #pragma unroll
        for (int c = 0; c < 4; c++) acc[n][c] = 0.f;

    #pragma unroll 8
    for (int k = 0; k < 64; k++) {
        float4 wv = *(const float4*)&wT[mat][k][ch0];
        float4 ha = *(const float4*)&hT[k][ng * 8];
        float4 hb = *(const float4*)&hT[k][ng * 8 + 4];
        float wr[4] = {wv.x, wv.y, wv.z, wv.w};
        float hr[8] = {ha.x, ha.y, ha.z, ha.w, hb.x, hb.y, hb.z, hb.w};
        #pragma unroll
        for (int n = 0; n < 8; n++)
            #pragma unroll
            for (int c = 0; c < 4; c++)
                acc[n][c] += hr[n] * wr[c];
    }

    if (!mat) {
        #pragma unroll
        for (int n = 0; n < 8; n++) {
            int gn = node0 + ng * 8 + n;
            if (gn < NN)
                *(float4*)(g_hs + (size_t)gn * 64 + ch0) =
                    make_float4(acc[n][0], acc[n][1], acc[n][2], acc[n][3]);
        }
    } else {
        #pragma unroll
        for (int n = 0; n < 8; n++) {
            int gn = node0 + ng * 8 + n;
            if (gn < NN) {
                union { __half2 h2[2]; uint2 u; } cv;
                cv.h2[0] = __floats2half2_rn(acc[n][0], acc[n][1]);
                cv.h2[1] = __floats2half2_rn(acc[n][2], acc[n][3]);
                *(uint2*)(g_zh + (size_t)gn * 64 + ch0) = cv.u;
            }
        }
    }

    __syncthreads();
    float* sp = &hT[0][0];
    if (mat) {
        float as0 = attn[ch0 + 0], as1 = attn[ch0 + 1];
        float as2 = attn[ch0 + 2], as3 = attn[ch0 + 3];
        float ad0 = attn[64 + ch0 + 0], ad1 = attn[64 + ch0 + 1];
        float ad2 = attn[64 + ch0 + 2], ad3 = attn[64 + ch0 + 3];
        int cg = t & 15;
        #pragma unroll
        for (int n = 0; n < 8; n++) {
            int node = ng * 8 + n;
            sp[node * 16 + cg] =
                acc[n][0] * as0 + acc[n][1] * as1 + acc[n][2] * as2 + acc[n][3] * as3;
            sp[1024 + node * 16 + cg] =
                acc[n][0] * ad0 + acc[n][1] * ad1 + acc[n][2] * ad2 + acc[n][3] * ad3;
        }
    }
    __syncthreads();
    if (t < 128) {
        int node = t & 63, sc = t >> 6;
        const float4* p = (const float4*)(sp + sc * 1024 + node * 16);
        float4 a = p[0], b = p[1], c = p[2], d = p[3];
        float s = ((a.x + a.y) + (a.z + a.w)) + ((b.x + b.y) + (b.z + b.w))
                + ((c.x + c.y) + (c.z + c.w)) + ((d.x + d.y) + (d.z + d.w));
        int gn = node0 + node;
        if (gn < NN) (sc ? g_sdst : g_ssrc)[gn] = s;
    }
}

// ---------------- fused: scatter + xform layer 1 + flag reset ----------------
__global__ __launch_bounds__(256) void k_sx(const int* __restrict__ src,
                                            const int* __restrict__ dst,
                                            const float* __restrict__ ew,
                                            const float* __restrict__ Wself,
                                            const float* __restrict__ Wfunc,
                                            const float* __restrict__ attn) {
    __shared__ float wT[2][64][64];
    __shared__ float hT[64][64];
    int blk = blockIdx.x;
    if (blk < HB) {
        if (blk == 0 && threadIdx.x < 128) g_flags[threadIdx.x] = 0;  // lookback reset
        int e = blk * 256 + threadIdx.x;
        int d = dst[e];
        int p = g_rowstart[d] + atomicSub(&g_cursor[d], 1) - 1;  // cursor back to 0
        g_edge[p] = make_int2(src[e], __float_as_int(ew[e]));
    } else {
        xform_body((blk - HB) * 64, Wself, Wfunc, attn, wT, hT);
    }
}

// ---------------- xform layer 2 ----------------------------------------------
__global__ __launch_bounds__(256) void k_xform2(const float* __restrict__ Wself,
                                                const float* __restrict__ Wfunc,
                                                const float* __restrict__ attn) {
    __shared__ float wT[2][64][64];
    __shared__ float hT[64][64];
    xform_body(blockIdx.x * 64, Wself, Wfunc, attn, wT, hT);
}

// ---------------- edge aggregation (warp-cooperative) + node epilogue --------
// 32 edges staged per warp pass: coalesced edge+ssrc loads, shfl broadcast,
// one coalesced 128B z-gather per edge.
__global__ __launch_bounds__(256) void k_agg(int layer, const float* __restrict__ linW,
                                             const float* __restrict__ linb,
                                             float* __restrict__ out) {
    __shared__ float w_sm[12][64];
    __shared__ float b_sm[12];
    int t = threadIdx.x;
    if (layer) {
        for (int idx = t; idx < 12 * 64; idx += 256)
            w_sm[idx >> 6][idx & 63] = linW[idx];
        if (t < 12) b_sm[t] = linb[t];
        __syncthreads();
    }

    int n = blockIdx.x * 8 + (t >> 5);
    int lane = t & 31;
    float c1 = g_c[layer * 2 + 0];
    float c0 = g_c[layer * 2 + 1];
    int beg = g_rowstart[n];
    int end = g_rowstart[n + 1];
    float base = g_sdst[n] + c0;
    const unsigned FULL = 0xffffffffu;

    float a0 = 0.f, a1 = 0.f, den = 0.f;

    for (int i0 = beg; i0 < end; i0 += 32) {
        int rem = end - i0;
        int idx = i0 + (lane < rem ? lane : 0);
        int2 e = g_edge[idx];
        float tsv = g_ssrc[e.x];
        float v = tsv + base + c1 * __int_as_float(e.y);
        v = fmaxf(v, NEG_SLOPE * v);
        float x = (lane < rem) ? __expf(v) : 0.f;
        int srcid = e.x;

        if (rem >= 32) {
            #pragma unroll 8
            for (int j = 0; j < 32; j++) {
                float xj = __shfl_sync(FULL, x, j);
                int   sj = __shfl_sync(FULL, srcid, j);
                float2 zf = __half22float2(
                    *(const __half2*)(g_zh + (size_t)sj * 64 + 2 * lane));
                den += xj;
                a0 += xj * zf.x;
                a1 += xj * zf.y;
            }
        } else {
            for (int j = 0; j < rem; j++) {
                float xj = __shfl_sync(FULL, x, j);
                int   sj = __shfl_sync(FULL, srcid, j);
                float2 zf = __half22float2(
                    *(const __half2*)(g_zh + (size_t)sj * 64 + 2 * lane));
                den += xj;
                a0 += xj * zf.x;
                a1 += xj * zf.y;
            }
        }
    }

    size_t o = (size_t)n * 64 + 2 * lane;
    float2 hv = *(const float2*)(g_h + o);
    float r0, r1;
    if (end > beg) {
        float inv = 1.0f / den;
        float2 hsv = *(const float2*)(g_hs + o);
        r0 = hsv.x + a0 * inv;
        r1 = hsv.y + a1 * inv;
    } else {
        r0 = hv.x; r1 = hv.y;
    }
    float hn0 = hv.x + fmaxf(r0, 0.f);
    float hn1 = hv.y + fmaxf(r1, 0.f);

    if (!layer) {
        *(float2*)(g_h + o) = make_float2(hn0, hn1);
    } else {
        float yv = 0.f;
        #pragma unroll
        for (int c = 0; c < 12; c++) {
            float2 wv = *(const float2*)&w_sm[c][2 * lane];
            float p = hn0 * wv.x + hn1 * wv.y;
            #pragma unroll
            for (int off = 16; off > 0; off >>= 1)
                p += __shfl_xor_sync(FULL, p, off);
            if (lane == c) yv = p + b_sm[c];
        }
        if (lane < 12) out[n * 12 + lane] = yv;
    }
}

// ---------------- launch -----------------------------------------------------
extern "C" void kernel_launch(void* const* d_in, const int* in_sizes, int n_in,
                              void* d_out, int out_size) {
    const float* feats   = (const float*)d_in[0];
    const float* e_w     = (const float*)d_in[1];
    const int*   src     = (const int*)d_in[4];
    const int*   dst     = (const int*)d_in[5];
    const float* emb_h_W = (const float*)d_in[6];
    const float* emb_h_b = (const float*)d_in[7];
    const float* emb_e_W = (const float*)d_in[8];
    const float* emb_e_b = (const float*)d_in[9];
    const float* W_self1 = (const float*)d_in[10];
    const float* W_func1 = (const float*)d_in[11];
    const float* attn1   = (const float*)d_in[12];
    const float* W_self2 = (const float*)d_in[13];
    const float* W_func2 = (const float*)d_in[14];
    const float* attn2   = (const float*)d_in[15];
    const float* lin1_W  = (const float*)d_in[16];
    const float* lin1_b  = (const float*)d_in[17];
    float* out = (float*)d_out;

    // ncu captures the 4th kernel launch -> k_agg(layer 0) this round
    k_pre<<<HB + EMB + 1, 256>>>(dst, feats, emb_h_W, emb_h_b,
                                 emb_e_W, emb_e_b, attn1, attn2);   // 0
    k_scan<<<NB_SCAN, 256>>>();                                     // 1
    k_sx<<<HB + XB, 256>>>(src, dst, e_w, W_self1, W_func1, attn1); // 2
    k_agg<<<NN / 8, 256>>>(0, lin1_W, lin1_b, out);                 // 3 <- ncu
    k_xform2<<<XB, 256>>>(W_self2, W_func2, attn2);                 // 4
    k_agg<<<NN / 8, 256>>>(1, lin1_W, lin1_b, out);                 // 5
}

// round 12
// speedup vs baseline: 1.7862x; 1.1010x over previous
#include <cuda_runtime.h>
#include <cuda_bf16.h>
#include <cuda_fp16.h>
#include <cstdint>

#define NN 100000
#define EE 1600000
#define DIN 24
#define DH 64
#define DOUT 12
#define NEG_SLOPE 0.01f

#define HB    (EE / 256)              // 6250 hist/scatter blocks
#define EMB   (NN / 4)                // 25000 embed blocks
#define NB_SCAN ((NN + 1023) / 1024)  // 98
#define XB    ((NN + 63) / 64)        // 1563 xform blocks

// dynamic smem partition sizes (halves)
#define HTILE (64 * 72)
#define WTILE (128 * 72)
#define XSMEM ((2 * HTILE + 2 * WTILE) * 2)   // 55296 bytes

// ---------------- scratch (static device globals; allocation-free) -----------
__device__ __align__(16) float  g_h[NN * DH];    // current node features
__device__ __align__(16) float  g_hs[NN * DH];   // h @ W_self.T
__device__ __align__(16) __half g_zh[NN * DH];   // h @ W_func.T (fp16, for gathers)
__device__ float g_ssrc[NN];
__device__ float g_sdst[NN];
__device__ int   g_rowstart[NN + 1];
__device__ int   g_cursor[NN];                   // counts; returns to 0 after scatter
__device__ __align__(16) int2 g_edge[EE];        // (src, bitcast(e_w)) sorted by dst
__device__ int   g_flags[128];                   // lookback flags (reset by k_scatter)
__device__ int   g_aggval[128];
__device__ int   g_prefval[128];
__device__ float g_c[4];                         // {c1_l1, c0_l1, c1_l2, c0_l2}

#define LDSM4(r0, r1, r2, r3, addr) \
    asm volatile("ldmatrix.sync.aligned.m8n8.x4.shared.b16 {%0,%1,%2,%3},[%4];" \
                 : "=r"(r0), "=r"(r1), "=r"(r2), "=r"(r3) : "r"(addr))
#define LDSM2(r0, r1, addr) \
    asm volatile("ldmatrix.sync.aligned.m8n8.x2.shared.b16 {%0,%1},[%2];" \
                 : "=r"(r0), "=r"(r1) : "r"(addr))
#define MMA16816(c, a0, a1, a2, a3, b0, b1) \
    asm volatile("mma.sync.aligned.m16n8k16.row.col.f32.f16.f16.f32 " \
                 "{%0,%1,%2,%3},{%4,%5,%6,%7},{%8,%9},{%0,%1,%2,%3};" \
                 : "+f"((c)[0]), "+f"((c)[1]), "+f"((c)[2]), "+f"((c)[3]) \
                 : "r"(a0), "r"(a1), "r"(a2), "r"(a3), "r"(b0), "r"(b1))

// ---------------- fused: hist + input embedding + edge coeffs ----------------
__global__ __launch_bounds__(256) void k_pre(
    const int* __restrict__ dst, const float* __restrict__ feats,
    const float* __restrict__ W, const float* __restrict__ b,
    const float* __restrict__ eW, const float* __restrict__ eb,
    const float* __restrict__ a1, const float* __restrict__ a2) {
    __shared__ float w_sm[64 * 25];
    __shared__ float f_sm[4 * 25];
    __shared__ float b_sm[64];
    __shared__ float csh[4][64];
    int t = threadIdx.x;
    int blk = blockIdx.x;

    if (blk < HB) {
        int e = blk * 256 + t;
        atomicAdd(&g_cursor[dst[e]], 1);
    } else if (blk < HB + EMB) {
        int node0 = (blk - HB) * 4;
        for (int idx = t; idx < 64 * 24; idx += 256)
            w_sm[(idx / 24) * 25 + (idx % 24)] = W[idx];
        for (int idx = t; idx < 4 * 24; idx += 256)
            f_sm[(idx / 24) * 25 + (idx % 24)] = feats[(node0 + idx / 24) * 24 + (idx % 24)];
        if (t < 64) b_sm[t] = b[t];
        __syncthreads();
        int ch = t & 63, nl = t >> 6;
        float acc = b_sm[ch];
        #pragma unroll
        for (int k = 0; k < 24; k++)
            acc += f_sm[nl * 25 + k] * w_sm[ch * 25 + k];
        g_h[(node0 + nl) * 64 + ch] = acc;
    } else {
        if (t < 64) {
            csh[0][t] = eW[t] * a1[128 + t];
            csh[1][t] = eb[t] * a1[128 + t];
            csh[2][t] = eW[t] * a2[128 + t];
            csh[3][t] = eb[t] * a2[128 + t];
        }
        __syncthreads();
        if (t < 4) {
            float s = 0.f;
            #pragma unroll
            for (int k = 0; k < 64; k++) s += csh[t][k];
            g_c[t] = s;
        }
    }
}

// ---------------- single-pass scan (decoupled lookback) ----------------------
__global__ __launch_bounds__(256) void k_scan() {
    __shared__ int sh[256];
    __shared__ int s_pref;
    int t = threadIdx.x;
    int bid = blockIdx.x;
    int base = bid * 1024 + t * 4;
    int v[4];
    #pragma unroll
    for (int i = 0; i < 4; i++) v[i] = (base + i < NN) ? g_cursor[base + i] : 0;
    int s = v[0] + v[1] + v[2] + v[3];
    sh[t] = s;
    __syncthreads();
    for (int off = 1; off < 256; off <<= 1) {
        int x = 0;
        if (t >= off) x = sh[t - off];
        __syncthreads();
        if (t >= off) sh[t] += x;
        __syncthreads();
    }
    int total = sh[255];
    int run = sh[t] - s;

    if (t == 0) {
        g_aggval[bid] = total;
        __threadfence();
        atomicExch(&g_flags[bid], 1);
        int pref = 0;
        int j = bid - 1;
        while (j >= 0) {
            int f;
            do { f = atomicAdd(&g_flags[j], 0); } while (f == 0);
            if (f == 2) { pref += atomicAdd(&g_prefval[j], 0); break; }
            pref += atomicAdd(&g_aggval[j], 0);
            j--;
        }
        g_prefval[bid] = pref + total;
        __threadfence();
        atomicExch(&g_flags[bid], 2);
        s_pref = pref;
    }
    __syncthreads();
    int add = s_pref;
    #pragma unroll
    for (int i = 0; i < 4; i++) {
        if (base + i < NN) g_rowstart[base + i] = add + run;
        run += v[i];
    }
    if (bid == 0 && t == 0) g_rowstart[NN] = EE;
}

// ---------------- scatter (atomicSub -> cursor back to 0) + flag reset -------
__global__ __launch_bounds__(256) void k_scatter(const int* __restrict__ src,
                                                 const int* __restrict__ dst,
                                                 const float* __restrict__ ew) {
    if (blockIdx.x == 0 && threadIdx.x < 128) g_flags[threadIdx.x] = 0;
    int e = blockIdx.x * 256 + threadIdx.x;
    int d = dst[e];
    int p = g_rowstart[d] + atomicSub(&g_cursor[d], 1) - 1;
    g_edge[p] = make_int2(src[e], __float_as_int(ew[e]));
}

// ---------------- node transform (split-fp16 tensor-core MMA) + scores -------
// D[64 nodes][128 ch] = h[64x64] @ [Wself;Wfunc]^T via m16n8k16 HMMA,
// h and W split hi+lo fp16 (3 MMAs) for ~fp32 accuracy.
__global__ __launch_bounds__(256) void k_xform(const float* __restrict__ Wself,
                                               const float* __restrict__ Wfunc,
                                               const float* __restrict__ attn) {
    extern __shared__ __half dsm[];
    __half* hHi = dsm;
    __half* hLo = hHi + HTILE;
    __half* wHi = hLo + HTILE;
    __half* wLo = wHi + WTILE;

    int t = threadIdx.x;
    int node0 = blockIdx.x * 64;

    // ---- stage h (fp32 -> hi/lo fp16), rows = node, 72-elem stride ----
    {
        int node = t >> 2;
        int k0 = (t & 3) * 16;
        int gn = node0 + node;
        float v[16];
        if (gn < NN) {
            #pragma unroll
            for (int i = 0; i < 4; i++) {
                float4 f = *(const float4*)(g_h + (size_t)gn * 64 + k0 + i * 4);
                v[i * 4 + 0] = f.x; v[i * 4 + 1] = f.y;
                v[i * 4 + 2] = f.z; v[i * 4 + 3] = f.w;
            }
        } else {
            #pragma unroll
            for (int i = 0; i < 16; i++) v[i] = 0.f;
        }
        #pragma unroll
        for (int i = 0; i < 16; i += 2) {
            __half h0 = __float2half_rn(v[i]), h1 = __float2half_rn(v[i + 1]);
            *(__half2*)(hHi + node * 72 + k0 + i) = __halves2half2(h0, h1);
            *(__half2*)(hLo + node * 72 + k0 + i) =
                __floats2half2_rn(v[i] - __half2float(h0), v[i + 1] - __half2float(h1));
        }
    }
    // ---- stage W (rows 0-63 self, 64-127 func) ----
    {
        int row = t >> 1;
        int k0 = (t & 1) * 32;
        const float* Wr = (row < 64) ? (Wself + row * 64) : (Wfunc + (row - 64) * 64);
        #pragma unroll
        for (int i = 0; i < 8; i++) {
            float4 f = *(const float4*)(Wr + k0 + i * 4);
            __half h0 = __float2half_rn(f.x), h1 = __float2half_rn(f.y);
            __half h2 = __float2half_rn(f.z), h3 = __float2half_rn(f.w);
            *(__half2*)(wHi + row * 72 + k0 + i * 4)     = __halves2half2(h0, h1);
            *(__half2*)(wHi + row * 72 + k0 + i * 4 + 2) = __halves2half2(h2, h3);
            *(__half2*)(wLo + row * 72 + k0 + i * 4) =
                __floats2half2_rn(f.x - __half2float(h0), f.y - __half2float(h1));
            *(__half2*)(wLo + row * 72 + k0 + i * 4 + 2) =
                __floats2half2_rn(f.z - __half2float(h2), f.w - __half2float(h3));
        }
    }
    __syncthreads();

    int w = t >> 5, lane = t & 31;
    int mt = w & 3;        // node tile: nodes mt*16..+15
    int mh = w >> 2;       // 0 = self (ch 0-63), 1 = func (ch 64-127)

    // A (h) ldmatrix base: lanes 0-15 -> rows, lanes 16-31 -> +8 cols
    uint32_t aHiB = (uint32_t)__cvta_generic_to_shared(
        hHi + (mt * 16 + (lane & 15)) * 72 + ((lane >> 4) << 3));
    uint32_t aLoB = (uint32_t)__cvta_generic_to_shared(
        hLo + (mt * 16 + (lane & 15)) * 72 + ((lane >> 4) << 3));
    // B (W) ldmatrix base for nt=0: lanes 0-7 rows @k0, 8-15 rows @k0+8
    uint32_t bHiB = (uint32_t)__cvta_generic_to_shared(
        wHi + (mh * 64 + (lane & 7)) * 72 + (((lane >> 3) & 1) << 3));
    uint32_t bLoB = (uint32_t)__cvta_generic_to_shared(
        wLo + (mh * 64 + (lane & 7)) * 72 + (((lane >> 3) & 1) << 3));

    float acc[8][4];
    #pragma unroll
    for (int nt = 0; nt < 8; nt++)
        #pragma unroll
        for (int i = 0; i < 4; i++) acc[nt][i] = 0.f;

    #pragma unroll
    for (int ks = 0; ks < 4; ks++) {
        uint32_t ah0, ah1, ah2, ah3, al0, al1, al2, al3;
        LDSM4(ah0, ah1, ah2, ah3, aHiB + ks * 32);
        LDSM4(al0, al1, al2, al3, aLoB + ks * 32);
        #pragma unroll
        for (int nt = 0; nt < 8; nt++) {
            uint32_t bh0, bh1, bl0, bl1;
            LDSM2(bh0, bh1, bHiB + nt * (8 * 72 * 2) + ks * 32);
            LDSM2(bl0, bl1, bLoB + nt * (8 * 72 * 2) + ks * 32);
            MMA16816(acc[nt], ah0, ah1, ah2, ah3, bh0, bh1);
            MMA16816(acc[nt], ah0, ah1, ah2, ah3, bl0, bl1);
            MMA16816(acc[nt], al0, al1, al2, al3, bh0, bh1);
        }
    }

    // ---- epilogue: C fragment {c0,c1}=row lane/4, {c2,c3}=row lane/4+8 ----
    int row = lane >> 2;
    int col2 = (lane & 3) * 2;
    int gnl = node0 + mt * 16 + row;
    int gnh = gnl + 8;

    if (mh == 0) {
        #pragma unroll
        for (int nt = 0; nt < 8; nt++) {
            int ch = nt * 8 + col2;
            if (gnl < NN)
                *(float2*)(g_hs + (size_t)gnl * 64 + ch) = make_float2(acc[nt][0], acc[nt][1]);
            if (gnh < NN)
                *(float2*)(g_hs + (size_t)gnh * 64 + ch) = make_float2(acc[nt][2], acc[nt][3]);
        }
    } else {
        float psl = 0.f, psh = 0.f, pdl = 0.f, pdh = 0.f;
        #pragma unroll
        for (int nt = 0; nt < 8; nt++) {
            int chF = nt * 8 + col2;   // func-local channel
            if (gnl < NN)
                *(__half2*)(g_zh + (size_t)gnl * 64 + chF) =
                    __floats2half2_rn(acc[nt][0], acc[nt][1]);
            if (gnh < NN)
                *(__half2*)(g_zh + (size_t)gnh * 64 + chF) =
                    __floats2half2_rn(acc[nt][2], acc[nt][3]);
            float as0 = attn[chF], as1 = attn[chF + 1];
            float ad0 = attn[64 + chF], ad1 = attn[64 + chF + 1];
            psl += acc[nt][0] * as0 + acc[nt][1] * as1;
            psh += acc[nt][2] * as0 + acc[nt][3] * as1;
            pdl += acc[nt][0] * ad0 + acc[nt][1] * ad1;
            pdh += acc[nt][2] * ad0 + acc[nt][3] * ad1;
        }
        const unsigned FULL = 0xffffffffu;
        #pragma unroll
        for (int off = 1; off <= 2; off <<= 1) {
            psl += __shfl_xor_sync(FULL, psl, off);
            psh += __shfl_xor_sync(FULL, psh, off);
            pdl += __shfl_xor_sync(FULL, pdl, off);
            pdh += __shfl_xor_sync(FULL, pdh, off);
        }
        if ((lane & 3) == 0) {
            if (gnl < NN) { g_ssrc[gnl] = psl; g_sdst[gnl] = pdl; }
            if (gnh < NN) { g_ssrc[gnh] = psh; g_sdst[gnh] = pdh; }
        }
    }
}

// ---------------- edge aggregation (warp-cooperative) + node epilogue --------
__global__ __launch_bounds__(256) void k_agg(int layer, const float* __restrict__ linW,
                                             const float* __restrict__ linb,
                                             float* __restrict__ out) {
    __shared__ float w_sm[12][64];
    __shared__ float b_sm[12];
    int t = threadIdx.x;
    if (layer) {
        for (int idx = t; idx < 12 * 64; idx += 256)
            w_sm[idx >> 6][idx & 63] = linW[idx];
        if (t < 12) b_sm[t] = linb[t];
        __syncthreads();
    }

    int n = blockIdx.x * 8 + (t >> 5);
    int lane = t & 31;
    float c1 = g_c[layer * 2 + 0];
    float c0 = g_c[layer * 2 + 1];
    int beg = g_rowstart[n];
    int end = g_rowstart[n + 1];
    float base = g_sdst[n] + c0;
    const unsigned FULL = 0xffffffffu;

    float a0 = 0.f, a1 = 0.f, den = 0.f;

    for (int i0 = beg; i0 < end; i0 += 32) {
        int rem = end - i0;
        if (rem > 32) rem = 32;
        int idx = i0 + (lane < rem ? lane : 0);
        int2 e = g_edge[idx];
        float tsv = g_ssrc[e.x];
        float v = tsv + base + c1 * __int_as_float(e.y);
        v = fmaxf(v, NEG_SLOPE * v);
        float x = (lane < rem) ? __expf(v) : 0.f;
        int srcid = e.x;

        int j = 0;
        for (; j + 8 <= rem; j += 8) {
            #pragma unroll
            for (int jj = 0; jj < 8; jj++) {
                float xj = __shfl_sync(FULL, x, j + jj);
                int   sj = __shfl_sync(FULL, srcid, j + jj);
                float2 zf = __half22float2(
                    *(const __half2*)(g_zh + (size_t)sj * 64 + 2 * lane));
                den += xj;
                a0 += xj * zf.x;
                a1 += xj * zf.y;
            }
        }
        for (; j < rem; j++) {
            float xj = __shfl_sync(FULL, x, j);
            int   sj = __shfl_sync(FULL, srcid, j);
            float2 zf = __half22float2(
                *(const __half2*)(g_zh + (size_t)sj * 64 + 2 * lane));
            den += xj;
            a0 += xj * zf.x;
            a1 += xj * zf.y;
        }
    }

    size_t o = (size_t)n * 64 + 2 * lane;
    float2 hv = *(const float2*)(g_h + o);
    float r0, r1;
    if (end > beg) {
        float inv = 1.0f / den;
        float2 hsv = *(const float2*)(g_hs + o);
        r0 = hsv.x + a0 * inv;
        r1 = hsv.y + a1 * inv;
    } else {
        r0 = hv.x; r1 = hv.y;
    }
    float hn0 = hv.x + fmaxf(r0, 0.f);
    float hn1 = hv.y + fmaxf(r1, 0.f);

    if (!layer) {
        *(float2*)(g_h + o) = make_float2(hn0, hn1);
    } else {
        float yv = 0.f;
        #pragma unroll
        for (int c = 0; c < 12; c++) {
            float2 wv = *(const float2*)&w_sm[c][2 * lane];
            float p = hn0 * wv.x + hn1 * wv.y;
            #pragma unroll
            for (int off = 16; off > 0; off >>= 1)
                p += __shfl_xor_sync(FULL, p, off);
            if (lane == c) yv = p + b_sm[c];
        }
        if (lane < 12) out[n * 12 + lane] = yv;
    }
}

// ---------------- launch -----------------------------------------------------
extern "C" void kernel_launch(void* const* d_in, const int* in_sizes, int n_in,
                              void* d_out, int out_size) {
    const float* feats   = (const float*)d_in[0];
    const float* e_w     = (const float*)d_in[1];
    const int*   src     = (const int*)d_in[4];
    const int*   dst     = (const int*)d_in[5];
    const float* emb_h_W = (const float*)d_in[6];
    const float* emb_h_b = (const float*)d_in[7];
    const float* emb_e_W = (const float*)d_in[8];
    const float* emb_e_b = (const float*)d_in[9];
    const float* W_self1 = (const float*)d_in[10];
    const float* W_func1 = (const float*)d_in[11];
    const float* attn1   = (const float*)d_in[12];
    const float* W_self2 = (const float*)d_in[13];
    const float* W_func2 = (const float*)d_in[14];
    const float* attn2   = (const float*)d_in[15];
    const float* lin1_W  = (const float*)d_in[16];
    const float* lin1_b  = (const float*)d_in[17];
    float* out = (float*)d_out;

    cudaFuncSetAttribute(k_xform, cudaFuncAttributeMaxDynamicSharedMemorySize, XSMEM);

    // ncu captures the 4th kernel launch -> k_xform (L1, tensor path)
    k_pre<<<HB + EMB + 1, 256>>>(dst, feats, emb_h_W, emb_h_b,
                                 emb_e_W, emb_e_b, attn1, attn2);   // 0
    k_scan<<<NB_SCAN, 256>>>();                                     // 1
    k_scatter<<<HB, 256>>>(src, dst, e_w);                          // 2
    k_xform<<<XB, 256, XSMEM>>>(W_self1, W_func1, attn1);           // 3 <- ncu
    k_agg<<<NN / 8, 256>>>(0, lin1_W, lin1_b, out);                 // 4
    k_xform<<<XB, 256, XSMEM>>>(W_self2, W_func2, attn2);           // 5
    k_agg<<<NN / 8, 256>>>(1, lin1_W, lin1_b, out);                 // 6
}

// round 13
// speedup vs baseline: 1.9122x; 1.0706x over previous
#include <cuda_runtime.h>
#include <cuda_bf16.h>
#include <cuda_fp16.h>
#include <cstdint>

#define NN 100000
#define EE 1600000
#define DIN 24
#define DH 64
#define DOUT 12
#define NEG_SLOPE 0.01f

#define HB    (EE / 256)              // 6250 hist/scatter blocks
#define EMB   (NN / 4)                // 25000 embed blocks
#define NB_SCAN ((NN + 1023) / 1024)  // 98
#define XB2   ((NN + 127) / 128)      // 782 xform blocks (128 nodes each)

// ---------------- scratch (static device globals; allocation-free) -----------
__device__ __align__(16) float  g_h[NN * DH];    // current node features
__device__ __align__(16) float  g_hs[NN * DH];   // h @ W_self.T
__device__ __align__(16) __half g_zh[NN * DH];   // h @ W_func.T (fp16, for gathers)
__device__ float g_ssrc[NN];
__device__ float g_sdst[NN];
__device__ int   g_rowstart[NN + 1];
__device__ int   g_cursor[NN];                   // counts; returns to 0 after scatter
__device__ __align__(16) int2 g_edge[EE];        // (src, bitcast(e_w)) sorted by dst
__device__ int   g_flags[128];                   // lookback flags (reset by k_scatter)
__device__ int   g_aggval[128];
__device__ int   g_prefval[128];
__device__ float g_c[4];                         // {c1_l1, c0_l1, c1_l2, c0_l2}

#define LDSM4(r0, r1, r2, r3, addr) \
    asm volatile("ldmatrix.sync.aligned.m8n8.x4.shared.b16 {%0,%1,%2,%3},[%4];" \
                 : "=r"(r0), "=r"(r1), "=r"(r2), "=r"(r3) : "r"(addr))
#define LDSM2(r0, r1, addr) \
    asm volatile("ldmatrix.sync.aligned.m8n8.x2.shared.b16 {%0,%1},[%2];" \
                 : "=r"(r0), "=r"(r1) : "r"(addr))
#define MMA16816(c, a0, a1, a2, a3, b0, b1) \
    asm volatile("mma.sync.aligned.m16n8k16.row.col.f32.f16.f16.f32 " \
                 "{%0,%1,%2,%3},{%4,%5,%6,%7},{%8,%9},{%0,%1,%2,%3};" \
                 : "+f"((c)[0]), "+f"((c)[1]), "+f"((c)[2]), "+f"((c)[3]) \
                 : "r"(a0), "r"(a1), "r"(a2), "r"(a3), "r"(b0), "r"(b1))

// ---------------- fused: hist + input embedding + edge coeffs ----------------
__global__ __launch_bounds__(256) void k_pre(
    const int* __restrict__ dst, const float* __restrict__ feats,
    const float* __restrict__ W, const float* __restrict__ b,
    const float* __restrict__ eW, const float* __restrict__ eb,
    const float* __restrict__ a1, const float* __restrict__ a2) {
    __shared__ float w_sm[64 * 25];
    __shared__ float f_sm[4 * 25];
    __shared__ float b_sm[64];
    __shared__ float csh[4][64];
    int t = threadIdx.x;
    int blk = blockIdx.x;

    if (blk < HB) {
        int e = blk * 256 + t;
        atomicAdd(&g_cursor[dst[e]], 1);
    } else if (blk < HB + EMB) {
        int node0 = (blk - HB) * 4;
        for (int idx = t; idx < 64 * 24; idx += 256)
            w_sm[(idx / 24) * 25 + (idx % 24)] = W[idx];
        for (int idx = t; idx < 4 * 24; idx += 256)
            f_sm[(idx / 24) * 25 + (idx % 24)] = feats[(node0 + idx / 24) * 24 + (idx % 24)];
        if (t < 64) b_sm[t] = b[t];
        __syncthreads();
        int ch = t & 63, nl = t >> 6;
        float acc = b_sm[ch];
        #pragma unroll
        for (int k = 0; k < 24; k++)
            acc += f_sm[nl * 25 + k] * w_sm[ch * 25 + k];
        g_h[(node0 + nl) * 64 + ch] = acc;
    } else {
        if (t < 64) {
            csh[0][t] = eW[t] * a1[128 + t];
            csh[1][t] = eb[t] * a1[128 + t];
            csh[2][t] = eW[t] * a2[128 + t];
            csh[3][t] = eb[t] * a2[128 + t];
        }
        __syncthreads();
        if (t < 4) {
            float s = 0.f;
            #pragma unroll
            for (int k = 0; k < 64; k++) s += csh[t][k];
            g_c[t] = s;
        }
    }
}

// ---------------- single-pass scan (decoupled lookback) ----------------------
__global__ __launch_bounds__(256) void k_scan() {
    __shared__ int sh[256];
    __shared__ int s_pref;
    int t = threadIdx.x;
    int bid = blockIdx.x;
    int base = bid * 1024 + t * 4;
    int v[4];
    #pragma unroll
    for (int i = 0; i < 4; i++) v[i] = (base + i < NN) ? g_cursor[base + i] : 0;
    int s = v[0] + v[1] + v[2] + v[3];
    sh[t] = s;
    __syncthreads();
    for (int off = 1; off < 256; off <<= 1) {
        int x = 0;
        if (t >= off) x = sh[t - off];
        __syncthreads();
        if (t >= off) sh[t] += x;
        __syncthreads();
    }
    int total = sh[255];
    int run = sh[t] - s;

    if (t == 0) {
        g_aggval[bid] = total;
        __threadfence();
        atomicExch(&g_flags[bid], 1);
        int pref = 0;
        int j = bid - 1;
        while (j >= 0) {
            int f;
            do { f = atomicAdd(&g_flags[j], 0); } while (f == 0);
            if (f == 2) { pref += atomicAdd(&g_prefval[j], 0); break; }
            pref += atomicAdd(&g_aggval[j], 0);
            j--;
        }
        g_prefval[bid] = pref + total;
        __threadfence();
        atomicExch(&g_flags[bid], 2);
        s_pref = pref;
    }
    __syncthreads();
    int add = s_pref;
    #pragma unroll
    for (int i = 0; i < 4; i++) {
        if (base + i < NN) g_rowstart[base + i] = add + run;
        run += v[i];
    }
    if (bid == 0 && t == 0) g_rowstart[NN] = EE;
}

// ---------------- scatter (atomicSub -> cursor back to 0) + flag reset -------
__global__ __launch_bounds__(256) void k_scatter(const int* __restrict__ src,
                                                 const int* __restrict__ dst,
                                                 const float* __restrict__ ew) {
    if (blockIdx.x == 0 && threadIdx.x < 128) g_flags[threadIdx.x] = 0;
    int e = blockIdx.x * 256 + threadIdx.x;
    int d = dst[e];
    int p = g_rowstart[d] + atomicSub(&g_cursor[d], 1) - 1;
    g_edge[p] = make_int2(src[e], __float_as_int(ew[e]));
}

// ---------------- node transform (fp16 tensor-core MMA) + scores -------------
// 128 nodes/block. D[128n][128ch] = h[128x64] @ [Wself;Wfunc]^T, m16n8k16 HMMA.
// Warp (mh, mtp) computes node tiles {mtp, mtp+4} x 64ch of matrix mh,
// reusing each B fragment for both node tiles.
__global__ __launch_bounds__(256) void k_xform(const float* __restrict__ Wself,
                                               const float* __restrict__ Wfunc,
                                               const float* __restrict__ attn) {
    __shared__ __half hSm[128 * 72];   // 18KB  [node][k]
    __shared__ __half wSm[128 * 72];   // 18KB  [row][k], rows 0-63 self, 64-127 func
    int t = threadIdx.x;
    int node0 = blockIdx.x * 128;

    // ---- stage h -> fp16 ----
    {
        int node = t >> 1;
        int k0 = (t & 1) * 32;
        int gn = node0 + node;
        #pragma unroll
        for (int i = 0; i < 8; i++) {
            float4 f = (gn < NN) ? *(const float4*)(g_h + (size_t)gn * 64 + k0 + i * 4)
                                 : make_float4(0.f, 0.f, 0.f, 0.f);
            *(__half2*)(hSm + node * 72 + k0 + i * 4)     = __floats2half2_rn(f.x, f.y);
            *(__half2*)(hSm + node * 72 + k0 + i * 4 + 2) = __floats2half2_rn(f.z, f.w);
        }
    }
    // ---- stage W -> fp16 ----
    {
        int row = t >> 1;
        int k0 = (t & 1) * 32;
        const float* Wr = (row < 64) ? (Wself + row * 64) : (Wfunc + (row - 64) * 64);
        #pragma unroll
        for (int i = 0; i < 8; i++) {
            float4 f = *(const float4*)(Wr + k0 + i * 4);
            *(__half2*)(wSm + row * 72 + k0 + i * 4)     = __floats2half2_rn(f.x, f.y);
            *(__half2*)(wSm + row * 72 + k0 + i * 4 + 2) = __floats2half2_rn(f.z, f.w);
        }
    }
    __syncthreads();

    int w = t >> 5, lane = t & 31;
    int mtp = w & 3;       // node tile pair: tiles mtp and mtp+4
    int mh = w >> 2;       // 0 = self, 1 = func

    uint32_t aB0 = (uint32_t)__cvta_generic_to_shared(
        hSm + (mtp * 16 + (lane & 15)) * 72 + ((lane >> 4) << 3));
    uint32_t aB1 = aB0 + (uint32_t)(64 * 72 * 2);   // tile mtp+4 = +64 nodes
    uint32_t bB = (uint32_t)__cvta_generic_to_shared(
        wSm + (mh * 64 + (lane & 7)) * 72 + (((lane >> 3) & 1) << 3));

    float acc[2][8][4];
    #pragma unroll
    for (int m = 0; m < 2; m++)
        #pragma unroll
        for (int nt = 0; nt < 8; nt++)
            #pragma unroll
            for (int i = 0; i < 4; i++) acc[m][nt][i] = 0.f;

    #pragma unroll
    for (int ks = 0; ks < 4; ks++) {
        uint32_t a00, a01, a02, a03, a10, a11, a12, a13;
        LDSM4(a00, a01, a02, a03, aB0 + ks * 32);
        LDSM4(a10, a11, a12, a13, aB1 + ks * 32);
        #pragma unroll
        for (int nt = 0; nt < 8; nt++) {
            uint32_t b0, b1;
            LDSM2(b0, b1, bB + nt * (8 * 72 * 2) + ks * 32);
            MMA16816(acc[0][nt], a00, a01, a02, a03, b0, b1);
            MMA16816(acc[1][nt], a10, a11, a12, a13, b0, b1);
        }
    }

    // ---- epilogue per node tile ----
    int row = lane >> 2;
    int col2 = (lane & 3) * 2;
    const unsigned FULL = 0xffffffffu;

    #pragma unroll
    for (int m = 0; m < 2; m++) {
        int gnl = node0 + (mtp + m * 4) * 16 + row;
        int gnh = gnl + 8;
        if (mh == 0) {
            #pragma unroll
            for (int nt = 0; nt < 8; nt++) {
                int ch = nt * 8 + col2;
                if (gnl < NN)
                    *(float2*)(g_hs + (size_t)gnl * 64 + ch) =
                        make_float2(acc[m][nt][0], acc[m][nt][1]);
                if (gnh < NN)
                    *(float2*)(g_hs + (size_t)gnh * 64 + ch) =
                        make_float2(acc[m][nt][2], acc[m][nt][3]);
            }
        } else {
            float psl = 0.f, psh = 0.f, pdl = 0.f, pdh = 0.f;
            #pragma unroll
            for (int nt = 0; nt < 8; nt++) {
                int chF = nt * 8 + col2;
                if (gnl < NN)
                    *(__half2*)(g_zh + (size_t)gnl * 64 + chF) =
                        __floats2half2_rn(acc[m][nt][0], acc[m][nt][1]);
                if (gnh < NN)
                    *(__half2*)(g_zh + (size_t)gnh * 64 + chF) =
                        __floats2half2_rn(acc[m][nt][2], acc[m][nt][3]);
                float as0 = attn[chF], as1 = attn[chF + 1];
                float ad0 = attn[64 + chF], ad1 = attn[64 + chF + 1];
                psl += acc[m][nt][0] * as0 + acc[m][nt][1] * as1;
                psh += acc[m][nt][2] * as0 + acc[m][nt][3] * as1;
                pdl += acc[m][nt][0] * ad0 + acc[m][nt][1] * ad1;
                pdh += acc[m][nt][2] * ad0 + acc[m][nt][3] * ad1;
            }
            #pragma unroll
            for (int off = 1; off <= 2; off <<= 1) {
                psl += __shfl_xor_sync(FULL, psl, off);
                psh += __shfl_xor_sync(FULL, psh, off);
                pdl += __shfl_xor_sync(FULL, pdl, off);
                pdh += __shfl_xor_sync(FULL, pdh, off);
            }
            if ((lane & 3) == 0) {
                if (gnl < NN) { g_ssrc[gnl] = psl; g_sdst[gnl] = pdl; }
                if (gnh < NN) { g_ssrc[gnh] = psh; g_sdst[gnh] = pdh; }
            }
        }
    }
}

// ---------------- edge aggregation (warp-cooperative) + node epilogue --------
__global__ __launch_bounds__(256) void k_agg(int layer, const float* __restrict__ linW,
                                             const float* __restrict__ linb,
                                             float* __restrict__ out) {
    __shared__ float w_sm[12][64];
    __shared__ float b_sm[12];
    int t = threadIdx.x;
    if (layer) {
        for (int idx = t; idx < 12 * 64; idx += 256)
            w_sm[idx >> 6][idx & 63] = linW[idx];
        if (t < 12) b_sm[t] = linb[t];
        __syncthreads();
    }

    int n = blockIdx.x * 8 + (t >> 5);
    int lane = t & 31;
    float c1 = g_c[layer * 2 + 0];
    float c0 = g_c[layer * 2 + 1];
    int beg = g_rowstart[n];
    int end = g_rowstart[n + 1];
    float base = g_sdst[n] + c0;
    const unsigned FULL = 0xffffffffu;

    float a0 = 0.f, a1 = 0.f, den = 0.f;

    for (int i0 = beg; i0 < end; i0 += 32) {
        int rem = end - i0;
        if (rem > 32) rem = 32;
        int idx = i0 + (lane < rem ? lane : 0);
        int2 e = g_edge[idx];
        float tsv = g_ssrc[e.x];
        float v = tsv + base + c1 * __int_as_float(e.y);
        v = fmaxf(v, NEG_SLOPE * v);
        float x = (lane < rem) ? __expf(v) : 0.f;
        int srcid = e.x;

        int j = 0;
        for (; j + 8 <= rem; j += 8) {
            #pragma unroll
            for (int jj = 0; jj < 8; jj++) {
                float xj = __shfl_sync(FULL, x, j + jj);
                int   sj = __shfl_sync(FULL, srcid, j + jj);
                float2 zf = __half22float2(
                    *(const __half2*)(g_zh + (size_t)sj * 64 + 2 * lane));
                den += xj;
                a0 += xj * zf.x;
                a1 += xj * zf.y;
            }
        }
        for (; j < rem; j++) {
            float xj = __shfl_sync(FULL, x, j);
            int   sj = __shfl_sync(FULL, srcid, j);
            float2 zf = __half22float2(
                *(const __half2*)(g_zh + (size_t)sj * 64 + 2 * lane));
            den += xj;
            a0 += xj * zf.x;
            a1 += xj * zf.y;
        }
    }

    size_t o = (size_t)n * 64 + 2 * lane;
    float2 hv = *(const float2*)(g_h + o);
    float r0, r1;
    if (end > beg) {
        float inv = 1.0f / den;
        float2 hsv = *(const float2*)(g_hs + o);
        r0 = hsv.x + a0 * inv;
        r1 = hsv.y + a1 * inv;
    } else {
        r0 = hv.x; r1 = hv.y;
    }
    float hn0 = hv.x + fmaxf(r0, 0.f);
    float hn1 = hv.y + fmaxf(r1, 0.f);

    if (!layer) {
        *(float2*)(g_h + o) = make_float2(hn0, hn1);
    } else {
        float yv = 0.f;
        #pragma unroll
        for (int c = 0; c < 12; c++) {
            float2 wv = *(const float2*)&w_sm[c][2 * lane];
            float p = hn0 * wv.x + hn1 * wv.y;
            #pragma unroll
            for (int off = 16; off > 0; off >>= 1)
                p += __shfl_xor_sync(FULL, p, off);
            if (lane == c) yv = p + b_sm[c];
        }
        if (lane < 12) out[n * 12 + lane] = yv;
    }
}

// ---------------- launch -----------------------------------------------------
extern "C" void kernel_launch(void* const* d_in, const int* in_sizes, int n_in,
                              void* d_out, int out_size) {
    const float* feats   = (const float*)d_in[0];
    const float* e_w     = (const float*)d_in[1];
    const int*   src     = (const int*)d_in[4];
    const int*   dst     = (const int*)d_in[5];
    const float* emb_h_W = (const float*)d_in[6];
    const float* emb_h_b = (const float*)d_in[7];
    const float* emb_e_W = (const float*)d_in[8];
    const float* emb_e_b = (const float*)d_in[9];
    const float* W_self1 = (const float*)d_in[10];
    const float* W_func1 = (const float*)d_in[11];
    const float* attn1   = (const float*)d_in[12];
    const float* W_self2 = (const float*)d_in[13];
    const float* W_func2 = (const float*)d_in[14];
    const float* attn2   = (const float*)d_in[15];
    const float* lin1_W  = (const float*)d_in[16];
    const float* lin1_b  = (const float*)d_in[17];
    float* out = (float*)d_out;

    // ncu captures the 4th kernel launch -> k_xform (L1, plain-fp16 path)
    k_pre<<<HB + EMB + 1, 256>>>(dst, feats, emb_h_W, emb_h_b,
                                 emb_e_W, emb_e_b, attn1, attn2);   // 0
    k_scan<<<NB_SCAN, 256>>>();                                     // 1
    k_scatter<<<HB, 256>>>(src, dst, e_w);                          // 2
    k_xform<<<XB2, 256>>>(W_self1, W_func1, attn1);                 // 3 <- ncu
    k_agg<<<NN / 8, 256>>>(0, lin1_W, lin1_b, out);                 // 4
    k_xform<<<XB2, 256>>>(W_self2, W_func2, attn2);                 // 5
    k_agg<<<NN / 8, 256>>>(1, lin1_W, lin1_b, out);                 // 6
}